// round 12
// baseline (speedup 1.0000x reference)
#include <cuda_runtime.h>
#include <cuda_fp16.h>
#include <math.h>
#include <stdint.h>

#define Bn 64
#define Sn 2048
#define Un 1024
#define Vn 50257
#define VnP 50304
#define Ln 8

// ---------------- scratch (device globals; no allocs allowed) ----------------
__device__ float g_q2[Bn * Un];
__device__ float g_q2p[32][Bn][Un];                    // q2 k-split partials
__device__ float g_ctxp[8][Bn][Un];                    // ctx s-split partials
__device__ float g_score[Bn * Sn];
__device__ float g_attnw[Bn * Sn];
__device__ float g_x[Bn * Un];
__device__ float g_zp16[16 * Bn * 3072];               // lstm k-split partials (i|g|o)
__device__ float g_logits[(size_t)Bn * Vn];
__device__ __half g_W1h[(size_t)Un * Un];              // W1^T [n][k] fp16
__device__ __half g_ench[(size_t)Bn * Sn * Un];        // enc as fp16
__device__ __half g_inph[2 * Bn * 2048];               // [plane][b][x|ctx] hi/lo

#define APLANE ((size_t)Bn * 2048)

// ======================= helpers =======================
__device__ __forceinline__ uint32_t smem_u32(const void* p) {
    uint32_t a;
    asm("{ .reg .u64 t; cvta.to.shared.u64 t, %1; cvt.u32.u64 %0, t; }" : "=r"(a) : "l"(p));
    return a;
}
__device__ __forceinline__ float tanh_fast(float x) {
    float y;
    asm("tanh.approx.f32 %0, %1;" : "=f"(y) : "f"(x));
    return y;
}
#define LDSM4(r0, r1, r2, r3, addr) \
    asm volatile("ldmatrix.sync.aligned.m8n8.x4.shared.b16 {%0,%1,%2,%3}, [%4];" \
                 : "=r"(r0), "=r"(r1), "=r"(r2), "=r"(r3) : "r"(addr))
#define LDSM4T(r0, r1, r2, r3, addr) \
    asm volatile("ldmatrix.sync.aligned.m8n8.x4.trans.shared.b16 {%0,%1,%2,%3}, [%4];" \
                 : "=r"(r0), "=r"(r1), "=r"(r2), "=r"(r3) : "r"(addr))
__device__ __forceinline__ void mma16816(float* d, const uint32_t* a, uint32_t b0, uint32_t b1) {
    asm volatile(
        "mma.sync.aligned.m16n8k16.row.col.f32.f16.f16.f32 "
        "{%0,%1,%2,%3}, {%4,%5,%6,%7}, {%8,%9}, {%0,%1,%2,%3};"
        : "+f"(d[0]), "+f"(d[1]), "+f"(d[2]), "+f"(d[3])
        : "r"(a[0]), "r"(a[1]), "r"(a[2]), "r"(a[3]), "r"(b0), "r"(b1));
}
__device__ __forceinline__ void cp16(uint32_t s, const void* g) {
    asm volatile("cp.async.ca.shared.global [%0], [%1], 16;" :: "r"(s), "l"(g));
}
#define CP_COMMIT() asm volatile("cp.async.commit_group;" ::: "memory")
#define CP_WAIT1() asm volatile("cp.async.wait_group 1;" ::: "memory")
#define CP_WAIT0() asm volatile("cp.async.wait_group 0;" ::: "memory")

// pack 8 floats -> hi uint4 and lo uint4 (lo = v - hi)
__device__ __forceinline__ void split8(const float* v, uint4& hi4, uint4& lo4) {
    __half2 h[4], l[4];
    #pragma unroll
    for (int i = 0; i < 4; i++) {
        h[i] = __floats2half2_rn(v[2 * i], v[2 * i + 1]);
        float2 hf = __half22float2(h[i]);
        l[i] = __floats2half2_rn(v[2 * i] - hf.x, v[2 * i + 1] - hf.y);
    }
    hi4.x = *reinterpret_cast<uint32_t*>(&h[0]);
    hi4.y = *reinterpret_cast<uint32_t*>(&h[1]);
    hi4.z = *reinterpret_cast<uint32_t*>(&h[2]);
    hi4.w = *reinterpret_cast<uint32_t*>(&h[3]);
    lo4.x = *reinterpret_cast<uint32_t*>(&l[0]);
    lo4.y = *reinterpret_cast<uint32_t*>(&l[1]);
    lo4.z = *reinterpret_cast<uint32_t*>(&l[2]);
    lo4.w = *reinterpret_cast<uint32_t*>(&l[3]);
}

// ---------------- init x = dec_input[:,0,:] ----------------
__global__ void copy_x_kernel(const float* __restrict__ dec) {
    int i = blockIdx.x * 256 + threadIdx.x;
    float v = dec[i];
    g_x[i] = v;
    int b = i >> 10, u = i & 1023;
    __half hi = __float2half_rn(v);
    g_inph[b * 2048 + u] = hi;
    g_inph[APLANE + b * 2048 + u] = __float2half_rn(v - __half2float(hi));
}

// ---------------- enc fp32 -> fp16 streaming ----------------
__global__ void ench_kernel(const float* __restrict__ enc) {
    size_t i = ((size_t)blockIdx.x * 256 + threadIdx.x) * 8;
    float4 v0 = *(const float4*)(enc + i);
    float4 v1 = *(const float4*)(enc + i + 4);
    __half2 h0 = __floats2half2_rn(v0.x, v0.y);
    __half2 h1 = __floats2half2_rn(v0.z, v0.w);
    __half2 h2 = __floats2half2_rn(v1.x, v1.y);
    __half2 h3 = __floats2half2_rn(v1.z, v1.w);
    uint4 u;
    u.x = *reinterpret_cast<uint32_t*>(&h0);
    u.y = *reinterpret_cast<uint32_t*>(&h1);
    u.z = *reinterpret_cast<uint32_t*>(&h2);
    u.w = *reinterpret_cast<uint32_t*>(&h3);
    *reinterpret_cast<uint4*>(g_ench + i) = u;
}

// ---------------- convert W1[k][n] -> g_W1h[n][k] fp16 ----------------
__global__ void conv_w1_kernel(const float* __restrict__ W1) {
    __shared__ float t[32][33];
    int n0 = blockIdx.x * 32, k0 = blockIdx.y * 32;
    int x = threadIdx.x, y = threadIdx.y;
    #pragma unroll
    for (int i = 0; i < 32; i += 8)
        t[y + i][x] = W1[(size_t)(k0 + y + i) * Un + n0 + x];
    __syncthreads();
    #pragma unroll
    for (int i = 0; i < 32; i += 8)
        g_W1h[(size_t)(n0 + y + i) * Un + k0 + x] = __float2half_rn(t[x][y + i]);
}

// ---------------- q2: 32-way k-split GEMM ----------------
__global__ __launch_bounds__(256) void q2_split_kernel(const float* __restrict__ qh,
                                                       const float* __restrict__ W2) {
    __shared__ float qs[32][68];
    const int tid = threadIdx.x;
    const int vt = blockIdx.x;
    const int ks = blockIdx.y;
    const int v = vt * 128 + (tid & 127);
    const int half = tid >> 7;
    const int k0 = ks * 32;

    for (int i = tid; i < 64 * 32; i += 256) {
        int b = i >> 5, k = i & 31;
        qs[k][b] = qh[b * Un + k0 + k];
    }
    __syncthreads();

    float acc[32];
    #pragma unroll
    for (int j = 0; j < 32; j++) acc[j] = 0.f;

    #pragma unroll 1
    for (int k = 0; k < 32; k++) {
        float w = W2[(size_t)(k0 + k) * Un + v];
        const float4* qrow = (const float4*)&qs[k][half * 32];
        #pragma unroll
        for (int j4 = 0; j4 < 8; j4++) {
            float4 q = qrow[j4];
            acc[j4 * 4 + 0] += w * q.x;
            acc[j4 * 4 + 1] += w * q.y;
            acc[j4 * 4 + 2] += w * q.z;
            acc[j4 * 4 + 3] += w * q.w;
        }
    }
    #pragma unroll
    for (int j = 0; j < 32; j++)
        g_q2p[ks][half * 32 + j][v] = acc[j];
}

__global__ void q2_fin_kernel(const float* __restrict__ b1, const float* __restrict__ b2) {
    int i = blockIdx.x * 256 + threadIdx.x;
    int b = i >> 10, v = i & 1023;
    float s = b1[v] + b2[v];
    #pragma unroll
    for (int ks = 0; ks < 32; ks++) s += g_q2p[ks][b][v];
    g_q2[i] = s;
}

// ========== HMMA fused score GEMM v4 (M=128, 512 thr, 3-stage pipe, 1 sync/iter) ==========
// stage s @ s*49152: A (128x64k fp16, 16KB) @+0, B (256n x 64k, 32KB) @+16384
#define SC_STG 49152
#define SCOFF_Q2 147456
#define SCOFF_AV 151552
#define SCOFF_RED 155648   // 512 floats
#define SC_SMEM 157696

__global__ __launch_bounds__(512, 1)
void score_mma_kernel(const float* __restrict__ attnV, const float* __restrict__ attnbV) {
    extern __shared__ char smem[];
    const uint32_t sb = smem_u32(smem);
    const int tid = threadIdx.x;
    const int lane = tid & 31;
    const int wid = tid >> 5;
    const int wm = wid & 3;      // rows wm*32..+32
    const int wn = wid >> 2;     // cols wn*64..+64 of 256-tile
    const int b = blockIdx.y;
    const int s0 = blockIdx.x * 128;

    float* q2s = (float*)(smem + SCOFF_Q2);
    float* avs = (float*)(smem + SCOFF_AV);
    float* red = (float*)(smem + SCOFF_RED);

    for (int i = tid; i < Un; i += 512) {
        q2s[i] = g_q2[b * Un + i];
        avs[i] = attnV[i];
    }

    const __half* panel = g_ench + ((size_t)b * Sn + s0) * Un;

    // A stage loader: 128 rows x 64k = 1024 chunks, 2/thread
    auto loadA = [&](int kk, int buf) {
        #pragma unroll
        for (int h = 0; h < 2; h++) {
            int id = h * 512 + tid;
            int r = id >> 3;
            int c = id & 7;
            cp16(sb + buf * SC_STG + r * 128 + ((c ^ (r & 7)) << 4),
                 panel + (size_t)r * Un + kk * 64 + c * 8);
        }
    };
    // B stage loader: 256n x 64k = 2048 chunks, 4/thread
    auto loadB = [&](int nt, int kk, int buf) {
        #pragma unroll
        for (int h = 0; h < 4; h++) {
            int ch = h * 512 + tid;
            int n = ch >> 3;
            int ck = ch & 7;
            cp16(sb + buf * SC_STG + 16384 + n * 128 + ((ck ^ (n & 7)) << 4),
                 g_W1h + (size_t)(nt * 256 + n) * Un + kk * 64 + ck * 8);
        }
    };

    // A ldsm bases: two 16-row tiles per warp
    const int ahi = lane >> 4;
    const int arow0 = wm * 32 + (lane & 15);
    const int arow1 = arow0 + 16;
    const uint32_t ao0 = arow0 * 128;
    const uint32_t ao1 = arow1 * 128;
    const int ax0 = arow0 & 7, ax1 = arow1 & 7;

    // B ldsm bases (4 col-tiles of 16)
    const int bhi = lane >> 4;
    uint32_t bno[4];
    int bxr[4];
    #pragma unroll
    for (int bt = 0; bt < 4; bt++) {
        int bn = wn * 64 + bt * 16 + (lane & 15);
        bno[bt] = bn * 128;
        bxr[bt] = bn & 7;
    }

    const int g = lane >> 2;
    const int t = lane & 3;
    float pa[4];
    #pragma unroll
    for (int i = 0; i < 4; i++) pa[i] = 0.f;

    float dacc[16][4];

    // prologue: stages for idx 0, 1
    loadA(0, 0); loadB(0, 0, 0); CP_COMMIT();
    loadA(1, 1); loadB(0, 1, 1); CP_COMMIT();

    #pragma unroll 1
    for (int idx = 0; idx < 64; idx++) {
        const int nt = idx >> 4;
        const int kk = idx & 15;
        const int buf = idx % 3;
        if (kk == 0) {
            #pragma unroll
            for (int i = 0; i < 16; i++)
                #pragma unroll
                for (int j = 0; j < 4; j++) dacc[i][j] = 0.f;
        }
        if (idx < 63) { CP_WAIT1(); } else { CP_WAIT0(); }
        __syncthreads();
        if (idx < 62) {
            int n = idx + 2;
            loadA(n & 15, n % 3);
            loadB(n >> 4, n & 15, n % 3);
            CP_COMMIT();
        }
        const uint32_t ast = sb + buf * SC_STG;
        const uint32_t bst = ast + 16384;
        #pragma unroll
        for (int kk2 = 0; kk2 < 4; kk2++) {
            uint32_t a0[4], a1[4];
            const int ck = kk2 * 2;
            LDSM4(a0[0], a0[1], a0[2], a0[3], ast + ao0 + (((ck + ahi) ^ ax0) << 4));
            LDSM4(a1[0], a1[1], a1[2], a1[3], ast + ao1 + (((ck + ahi) ^ ax1) << 4));
            const int bck = ck + bhi;
            #pragma unroll
            for (int bt = 0; bt < 4; bt++) {
                uint32_t q[4];
                LDSM4(q[0], q[1], q[2], q[3], bst + bno[bt] + ((bck ^ bxr[bt]) << 4));
                mma16816(dacc[0 + bt * 2 + 0], a0, q[0], q[2]);
                mma16816(dacc[0 + bt * 2 + 1], a0, q[1], q[3]);
                mma16816(dacc[8 + bt * 2 + 0], a1, q[0], q[2]);
                mma16816(dacc[8 + bt * 2 + 1], a1, q[1], q[3]);
            }
        }
        if (kk == 15) {
            // epilogue for this n-tile: tanh(D + q2) * attnV
            #pragma unroll
            for (int at = 0; at < 2; at++)
                #pragma unroll
                for (int bt = 0; bt < 4; bt++)
                    #pragma unroll
                    for (int h = 0; h < 2; h++) {
                        const float* dd = dacc[at * 8 + bt * 2 + h];
                        int c0 = nt * 256 + wn * 64 + bt * 16 + h * 8 + 2 * t;
                        float qa = q2s[c0], qb = q2s[c0 + 1];
                        float va = avs[c0], vb = avs[c0 + 1];
                        pa[at * 2 + 0] += tanh_fast(dd[0] + qa) * va + tanh_fast(dd[1] + qb) * vb;
                        pa[at * 2 + 1] += tanh_fast(dd[2] + qa) * va + tanh_fast(dd[3] + qb) * vb;
                    }
        }
    }
    #pragma unroll
    for (int i = 0; i < 4; i++) {
        pa[i] += __shfl_xor_sync(0xffffffffu, pa[i], 1);
        pa[i] += __shfl_xor_sync(0xffffffffu, pa[i], 2);
    }
    if (t == 0) {
        #pragma unroll
        for (int at = 0; at < 2; at++)
            #pragma unroll
            for (int hh = 0; hh < 2; hh++)
                red[wn * 128 + wm * 32 + at * 16 + hh * 8 + g] = pa[at * 2 + hh];
    }
    __syncthreads();
    if (tid < 128) {
        g_score[b * Sn + s0 + tid] =
            red[tid] + red[128 + tid] + red[256 + tid] + red[384 + tid] + attnbV[0];
    }
}

// ---------------- softmax over S ----------------
__global__ void softmax_s_kernel(float* __restrict__ out_attnw) {
    int b = blockIdx.x;
    int tid = threadIdx.x;
    __shared__ float red[256];
    float m = -1e30f;
    for (int s = tid; s < Sn; s += 256) m = fmaxf(m, g_score[b * Sn + s]);
    red[tid] = m; __syncthreads();
    for (int o = 128; o > 0; o >>= 1) { if (tid < o) red[tid] = fmaxf(red[tid], red[tid + o]); __syncthreads(); }
    m = red[0]; __syncthreads();
    float sum = 0.f;
    for (int s = tid; s < Sn; s += 256) {
        float e = expf(g_score[b * Sn + s] - m);
        g_attnw[b * Sn + s] = e;
        sum += e;
    }
    red[tid] = sum; __syncthreads();
    for (int o = 128; o > 0; o >>= 1) { if (tid < o) red[tid] += red[tid + o]; __syncthreads(); }
    float inv = 1.f / red[0];
    for (int s = tid; s < Sn; s += 256) {
        float w = g_attnw[b * Sn + s] * inv;
        g_attnw[b * Sn + s] = w;
        out_attnw[b * Sn + s] = w;
    }
}

// ---------------- ctx partials: 8 s-splits, half2 loads ----------------
__global__ void ctx_part_kernel() {
    int b = blockIdx.x;
    int u0 = (blockIdx.y * 128 + threadIdx.x) * 2;
    int ss = blockIdx.z;
    const __half2* e = (const __half2*)(g_ench + (size_t)b * Sn * Un +
                                        (size_t)(ss * 256) * Un + u0);
    const float* w = g_attnw + b * Sn + ss * 256;
    float ax = 0.f, ay = 0.f;
    #pragma unroll 4
    for (int s = 0; s < 256; s++) {
        float2 v = __half22float2(e[(size_t)s * (Un / 2)]);
        float ws = w[s];
        ax += ws * v.x;
        ay += ws * v.y;
    }
    g_ctxp[ss][b][u0] = ax;
    g_ctxp[ss][b][u0 + 1] = ay;
}

__global__ void ctx_fin_kernel() {
    int i = blockIdx.x * 256 + threadIdx.x;
    int b = i >> 10, u = i & 1023;
    float c = 0.f;
    #pragma unroll
    for (int ss = 0; ss < 8; ss++) c += g_ctxp[ss][b][u];
    __half hi = __float2half_rn(c);
    g_inph[b * 2048 + 1024 + u] = hi;
    g_inph[APLANE + b * 2048 + 1024 + u] = __float2half_rn(c - __half2float(hi));
}

// =================== LSTM GEMM: 16-way k-split pipelined split-fp16 HMMA ===================
__global__ __launch_bounds__(128)
void lstm_mma_kernel(const float* __restrict__ W) {
    __shared__ __align__(128) char sm[65536];
    const uint32_t sb = smem_u32(sm);
    const int tid = threadIdx.x, lane = tid & 31, wid = tid >> 5;
    const int wm = wid & 1, wn = wid >> 1;
    const int nt = blockIdx.x;
    const int ks = blockIdx.y;     // 16 splits of 128 k
    const int k0 = ks * 128;
    const int wcol0 = nt * 64 + (nt >= 16 ? 1024 : 0);
    const int zcol0 = nt * 64;

    float dacc[8][4];
    #pragma unroll
    for (int i = 0; i < 8; i++)
        #pragma unroll
        for (int j = 0; j < 4; j++) dacc[i][j] = 0.f;

    const int hi16 = lane >> 4;
    const int g8 = lane >> 3;
    const int r8 = lane & 7;
    const int arow0 = wm * 32 + (lane & 15);
    const int arow1 = arow0 + 16;

    auto loadW = [&](int kk, float* wv) {
        #pragma unroll
        for (int j = 0; j < 4; j++) {
            int ch = j * 128 + tid;
            int k = ch >> 3, c = ch & 7;
            const float* src = W + (size_t)(k0 + kk * 64 + k) * 4096 + wcol0 + c * 8;
            float4 s0 = *(const float4*)src;
            float4 s1 = *(const float4*)(src + 4);
            wv[j * 8 + 0] = s0.x; wv[j * 8 + 1] = s0.y; wv[j * 8 + 2] = s0.z; wv[j * 8 + 3] = s0.w;
            wv[j * 8 + 4] = s1.x; wv[j * 8 + 5] = s1.y; wv[j * 8 + 6] = s1.z; wv[j * 8 + 7] = s1.w;
        }
    };
    auto stsB = [&](const float* wv, int buf) {
        #pragma unroll
        for (int j = 0; j < 4; j++) {
            int ch = j * 128 + tid;
            int k = ch >> 3, c = ch & 7;
            uint4 hi4, lo4;
            split8(wv + j * 8, hi4, lo4);
            int off = 32768 + buf * 16384 + k * 128 + ((c ^ (k & 7)) << 4);
            *(uint4*)(sm + off) = hi4;
            *(uint4*)(sm + off + 8192) = lo4;
        }
    };
    auto cpA = [&](int kk, int st) {
        #pragma unroll
        for (int j = 0; j < 8; j++) {
            int ch = j * 128 + tid;
            int plane = ch >> 9, cc = ch & 511;
            int m = cc >> 3, c = cc & 7;
            cp16(sb + st * 16384 + plane * 8192 + m * 128 + ((c ^ (m & 7)) << 4),
                 g_inph + (size_t)plane * APLANE + (size_t)m * 2048 + k0 + kk * 64 + c * 8);
        }
    };

    float wv[32], wv2[32];
    loadW(0, wv);
    cpA(0, 0);
    CP_COMMIT();

    #pragma unroll 1
    for (int kk = 0; kk < 2; kk++) {
        const int buf = kk & 1;
        stsB(wv, buf);
        if (kk < 1) loadW(kk + 1, wv2);
        CP_WAIT0();
        __syncthreads();
        if (kk < 1) { cpA(kk + 1, buf ^ 1); CP_COMMIT(); }
        #pragma unroll
        for (int seg = 0; seg < 3; seg++) {
            const uint32_t abase = sb + buf * 16384 + (seg == 2 ? 8192 : 0);
            const uint32_t bbase = sb + 32768 + buf * 16384 + (seg == 1 ? 8192 : 0);
            #pragma unroll
            for (int kk2 = 0; kk2 < 4; kk2++) {
                uint32_t a0[4], a1[4];
                int ck = kk2 * 2 + hi16;
                LDSM4(a0[0], a0[1], a0[2], a0[3],
                      abase + arow0 * 128 + ((ck ^ (arow0 & 7)) << 4));
                LDSM4(a1[0], a1[1], a1[2], a1[3],
                      abase + arow1 * 128 + ((ck ^ (arow1 & 7)) << 4));
                int kloc = kk2 * 16 + (g8 & 1) * 8 + r8;
                #pragma unroll
                for (int bt = 0; bt < 2; bt++) {
                    int nchunk = wn * 4 + bt * 2 + (g8 >> 1);
                    uint32_t q[4];
                    LDSM4T(q[0], q[1], q[2], q[3],
                           bbase + kloc * 128 + ((nchunk ^ (kloc & 7)) << 4));
                    mma16816(dacc[0 + bt * 2 + 0], a0, q[0], q[1]);
                    mma16816(dacc[0 + bt * 2 + 1], a0, q[2], q[3]);
                    mma16816(dacc[4 + bt * 2 + 0], a1, q[0], q[1]);
                    mma16816(dacc[4 + bt * 2 + 1], a1, q[2], q[3]);
                }
            }
        }
        #pragma unroll
        for (int j = 0; j < 32; j++) wv[j] = wv2[j];
        __syncthreads();
    }
    const int g = lane >> 2;
    const int t = lane & 3;
    float* zp = g_zp16 + (size_t)ks * Bn * 3072;
    #pragma unroll
    for (int at = 0; at < 2; at++)
        #pragma unroll
        for (int bt = 0; bt < 2; bt++)
            #pragma unroll
            for (int h = 0; h < 2; h++) {
                const float* dd = dacc[at * 4 + bt * 2 + h];
                int c0 = zcol0 + wn * 32 + bt * 16 + h * 8 + 2 * t;
                int r0 = wm * 32 + at * 16 + g;
                zp[(size_t)r0 * 3072 + c0] = dd[0];
                zp[(size_t)r0 * 3072 + c0 + 1] = dd[1];
                zp[(size_t)(r0 + 8) * 3072 + c0] = dd[2];
                zp[(size_t)(r0 + 8) * 3072 + c0 + 1] = dd[3];
            }
}

// ---------------- LSTM activation: sum 16 partials ----------------
__global__ void lstm_act_kernel(const float* __restrict__ lb,
                                float* __restrict__ hs, float* __restrict__ cs,
                                int layer, int residual) {
    int b = blockIdx.x;
    int u = threadIdx.x;
    float zi = lb[u], zg = lb[2048 + u], zo = lb[3072 + u];
    #pragma unroll
    for (int ks = 0; ks < 16; ks++) {
        const float* zp = g_zp16 + ((size_t)ks * Bn + b) * 3072;
        zi += zp[u];
        zg += zp[1024 + u];
        zo += zp[2048 + u];
    }
    float c = (1.f / (1.f + expf(-zi))) * tanhf(zg);
    float h = (1.f / (1.f + expf(-zo))) * tanhf(c);
    size_t o = ((size_t)layer * Bn + b) * Un + u;
    hs[o] = h;
    cs[o] = c;
    float xo = g_x[b * Un + u];
    float xn = residual ? (h + xo) : h;
    g_x[b * Un + u] = xn;
    __half hhi = __float2half_rn(xn);
    g_inph[b * 2048 + u] = hhi;
    g_inph[APLANE + b * 2048 + u] = __float2half_rn(xn - __half2float(hhi));
}

// =================== dense GEMM: pipelined fused-conversion split-fp16 HMMA ===================
__global__ __launch_bounds__(128)
void dense_mma_kernel(const float* __restrict__ W, const float* __restrict__ db) {
    __shared__ __align__(128) char sm[65536];
    const uint32_t sb = smem_u32(sm);
    const int tid = threadIdx.x, lane = tid & 31, wid = tid >> 5;
    const int wm = wid & 1, wn = wid >> 1;
    const int n0 = blockIdx.x * 64;

    float dacc[8][4];
    #pragma unroll
    for (int i = 0; i < 8; i++)
        #pragma unroll
        for (int j = 0; j < 4; j++) dacc[i][j] = 0.f;

    const int hi16 = lane >> 4;
    const int g8 = lane >> 3;
    const int r8 = lane & 7;
    const int arow0 = wm * 32 + (lane & 15);
    const int arow1 = arow0 + 16;

    auto loadW = [&](int kk, float* wv) {
        #pragma unroll
        for (int j = 0; j < 4; j++) {
            int ch = j * 128 + tid;
            int k = ch >> 3, c = ch & 7;
            const float* src = W + (size_t)(kk * 64 + k) * Vn + n0 + c * 8;
            #pragma unroll
            for (int e = 0; e < 8; e++) {
                int ng = n0 + c * 8 + e;
                wv[j * 8 + e] = (ng < Vn) ? src[e] : 0.f;
            }
        }
    };
    auto stsB = [&](const float* wv, int buf) {
        #pragma unroll
        for (int j = 0; j < 4; j++) {
            int ch = j * 128 + tid;
            int k = ch >> 3, c = ch & 7;
            uint4 hi4, lo4;
            split8(wv + j * 8, hi4, lo4);
            int off = 32768 + buf * 16384 + k * 128 + ((c ^ (k & 7)) << 4);
            *(uint4*)(sm + off) = hi4;
            *(uint4*)(sm + off + 8192) = lo4;
        }
    };
    auto cpA = [&](int kk, int st) {
        #pragma unroll
        for (int j = 0; j < 8; j++) {
            int ch = j * 128 + tid;
            int plane = ch >> 9, cc = ch & 511;
            int m = cc >> 3, c = cc & 7;
            cp16(sb + st * 16384 + plane * 8192 + m * 128 + ((c ^ (m & 7)) << 4),
                 g_inph + (size_t)plane * APLANE + (size_t)m * 2048 + kk * 64 + c * 8);
        }
    };

    float wv[32], wv2[32];
    loadW(0, wv);
    cpA(0, 0);
    CP_COMMIT();

    #pragma unroll 1
    for (int kk = 0; kk < 16; kk++) {
        const int buf = kk & 1;
        stsB(wv, buf);
        if (kk < 15) loadW(kk + 1, wv2);
        CP_WAIT0();
        __syncthreads();
        if (kk < 15) { cpA(kk + 1, buf ^ 1); CP_COMMIT(); }
        #pragma unroll
        for (int seg = 0; seg < 3; seg++) {
            const uint32_t abase = sb + buf * 16384 + (seg == 2 ? 8192 : 0);
            const uint32_t bbase = sb + 32768 + buf * 16384 + (seg == 1 ? 8192 : 0);
            #pragma unroll
            for (int kk2 = 0; kk2 < 4; kk2++) {
                uint32_t a0[4], a1[4];
                int ck = kk2 * 2 + hi16;
                LDSM4(a0[0], a0[1], a0[2], a0[3],
                      abase + arow0 * 128 + ((ck ^ (arow0 & 7)) << 4));
                LDSM4(a1[0], a1[1], a1[2], a1[3],
                      abase + arow1 * 128 + ((ck ^ (arow1 & 7)) << 4));
                int kloc = kk2 * 16 + (g8 & 1) * 8 + r8;
                #pragma unroll
                for (int bt = 0; bt < 2; bt++) {
                    int nchunk = wn * 4 + bt * 2 + (g8 >> 1);
                    uint32_t q[4];
                    LDSM4T(q[0], q[1], q[2], q[3],
                           bbase + kloc * 128 + ((nchunk ^ (kloc & 7)) << 4));
                    mma16816(dacc[0 + bt * 2 + 0], a0, q[0], q[1]);
                    mma16816(dacc[0 + bt * 2 + 1], a0, q[2], q[3]);
                    mma16816(dacc[4 + bt * 2 + 0], a1, q[0], q[1]);
                    mma16816(dacc[4 + bt * 2 + 1], a1, q[2], q[3]);
                }
            }
        }
        #pragma unroll
        for (int j = 0; j < 32; j++) wv[j] = wv2[j];
        __syncthreads();
    }
    const int g = lane >> 2;
    const int t = lane & 3;
    #pragma unroll
    for (int at = 0; at < 2; at++)
        #pragma unroll
        for (int bt = 0; bt < 2; bt++)
            #pragma unroll
            for (int h = 0; h < 2; h++) {
                const float* dd = dacc[at * 4 + bt * 2 + h];
                int c0 = n0 + wn * 32 + bt * 16 + h * 8 + 2 * t;
                int r0 = wm * 32 + at * 16 + g;
                if (c0 < Vn) {
                    float bb = db[c0];
                    g_logits[(size_t)r0 * Vn + c0] = dd[0] + bb;
                    g_logits[(size_t)(r0 + 8) * Vn + c0] = dd[2] + bb;
                }
                if (c0 + 1 < Vn) {
                    float bb = db[c0 + 1];
                    g_logits[(size_t)r0 * Vn + c0 + 1] = dd[1] + bb;
                    g_logits[(size_t)(r0 + 8) * Vn + c0 + 1] = dd[3] + bb;
                }
            }
}

// ---------------- softmax over V -> probs ----------------
__global__ void softmax_v_kernel(float* __restrict__ probs) {
    int b = blockIdx.x;
    int tid = threadIdx.x;
    __shared__ float red[1024];
    const float* lg = g_logits + (size_t)b * Vn;
    float m = -1e30f;
    for (int j = tid; j < Vn; j += 1024) m = fmaxf(m, lg[j]);
    red[tid] = m; __syncthreads();
    for (int o = 512; o > 0; o >>= 1) { if (tid < o) red[tid] = fmaxf(red[tid], red[tid + o]); __syncthreads(); }
    m = red[0]; __syncthreads();
    float sum = 0.f;
    float* pb = probs + (size_t)b * Vn;
    for (int j = tid; j < Vn; j += 1024) {
        float e = expf(lg[j] - m);
        pb[j] = e;
        sum += e;
    }
    red[tid] = sum; __syncthreads();
    for (int o = 512; o > 0; o >>= 1) { if (tid < o) red[tid] += red[tid + o]; __syncthreads(); }
    float inv = 1.f / red[0];
    for (int j = tid; j < Vn; j += 1024) pb[j] *= inv;
}

// ---------------- launch ----------------
extern "C" void kernel_launch(void* const* d_in, const int* in_sizes, int n_in,
                              void* d_out, int out_size) {
    const float* enc = (const float*)d_in[0];
    const float* dec = (const float*)d_in[1];
    const float* qh  = (const float*)d_in[2];
    const float* W1  = (const float*)d_in[3];
    const float* b1  = (const float*)d_in[4];
    const float* W2  = (const float*)d_in[5];
    const float* b2  = (const float*)d_in[6];
    const float* aV  = (const float*)d_in[7];
    const float* abV = (const float*)d_in[8];
    const float* lW  = (const float*)d_in[9];
    const float* lb  = (const float*)d_in[10];
    const float* dW  = (const float*)d_in[11];
    const float* db  = (const float*)d_in[12];

    float* out   = (float*)d_out;
    float* probs = out;
    float* hs    = out + (size_t)Bn * Vn;
    float* cs    = hs + (size_t)Ln * Bn * Un;
    float* attnw = cs + (size_t)Ln * Bn * Un;

    static const int RES[8] = {0, 0, 1, 1, 1, 1, 1, 0};

    cudaFuncSetAttribute(score_mma_kernel,
                         cudaFuncAttributeMaxDynamicSharedMemorySize, SC_SMEM);

    copy_x_kernel<<<256, 256>>>(dec);
    ench_kernel<<<65536, 256>>>(enc);
    conv_w1_kernel<<<dim3(32, 32), dim3(32, 8)>>>(W1);
    q2_split_kernel<<<dim3(8, 32), 256>>>(qh, W2);
    q2_fin_kernel<<<256, 256>>>(b1, b2);
    score_mma_kernel<<<dim3(Sn / 128, Bn), 512, SC_SMEM>>>(aV, abV);
    softmax_s_kernel<<<Bn, 256>>>(attnw);
    ctx_part_kernel<<<dim3(Bn, 4, 8), 128>>>();
    ctx_fin_kernel<<<256, 256>>>();

    for (int l = 0; l < Ln; l++) {
        lstm_mma_kernel<<<dim3(48, 16), 128>>>(lW + (size_t)l * 2048 * 4096);
        lstm_act_kernel<<<Bn, 1024>>>(lb + (size_t)l * 4096, hs, cs, l, RES[l]);
    }

    dense_mma_kernel<<<VnP / 64, 128>>>(dW, db);
    softmax_v_kernel<<<Bn, 1024>>>(probs);
}

// round 13
// speedup vs baseline: 1.0046x; 1.0046x over previous
#include <cuda_runtime.h>
#include <cuda_fp16.h>
#include <math.h>
#include <stdint.h>

#define Bn 64
#define Sn 2048
#define Un 1024
#define Vn 50257
#define VnP 50304
#define Ln 8

// ---------------- scratch (device globals; no allocs allowed) ----------------
__device__ float g_q2[Bn * Un];
__device__ float g_q2p[32][Bn][Un];                    // q2 k-split partials
__device__ float g_ctxp[8][Bn][Un];                    // ctx s-split partials
__device__ float g_score[Bn * Sn];
__device__ float g_attnw[Bn * Sn];
__device__ float g_x[Bn * Un];
__device__ float g_zp16[16 * Bn * 3072];               // lstm k-split partials (i|g|o)
__device__ float g_logits[(size_t)Bn * Vn];
__device__ __half g_W1h[(size_t)Un * Un];              // W1^T [n][k] fp16
__device__ __half g_ench[(size_t)Bn * Sn * Un];        // enc as fp16
__device__ __half g_inph[2 * Bn * 2048];               // [plane][b][x|ctx] hi/lo

#define APLANE ((size_t)Bn * 2048)

// ======================= helpers =======================
__device__ __forceinline__ uint32_t smem_u32(const void* p) {
    uint32_t a;
    asm("{ .reg .u64 t; cvta.to.shared.u64 t, %1; cvt.u32.u64 %0, t; }" : "=r"(a) : "l"(p));
    return a;
}
__device__ __forceinline__ float tanh_fast(float x) {
    float y;
    asm("tanh.approx.f32 %0, %1;" : "=f"(y) : "f"(x));
    return y;
}
#define LDSM4(r0, r1, r2, r3, addr) \
    asm volatile("ldmatrix.sync.aligned.m8n8.x4.shared.b16 {%0,%1,%2,%3}, [%4];" \
                 : "=r"(r0), "=r"(r1), "=r"(r2), "=r"(r3) : "r"(addr))
#define LDSM4T(r0, r1, r2, r3, addr) \
    asm volatile("ldmatrix.sync.aligned.m8n8.x4.trans.shared.b16 {%0,%1,%2,%3}, [%4];" \
                 : "=r"(r0), "=r"(r1), "=r"(r2), "=r"(r3) : "r"(addr))
__device__ __forceinline__ void mma16816(float* d, const uint32_t* a, uint32_t b0, uint32_t b1) {
    asm volatile(
        "mma.sync.aligned.m16n8k16.row.col.f32.f16.f16.f32 "
        "{%0,%1,%2,%3}, {%4,%5,%6,%7}, {%8,%9}, {%0,%1,%2,%3};"
        : "+f"(d[0]), "+f"(d[1]), "+f"(d[2]), "+f"(d[3])
        : "r"(a[0]), "r"(a[1]), "r"(a[2]), "r"(a[3]), "r"(b0), "r"(b1));
}
__device__ __forceinline__ void cp16(uint32_t s, const void* g) {
    asm volatile("cp.async.ca.shared.global [%0], [%1], 16;" :: "r"(s), "l"(g));
}
#define CP_COMMIT() asm volatile("cp.async.commit_group;" ::: "memory")
#define CP_WAIT1() asm volatile("cp.async.wait_group 1;" ::: "memory")
#define CP_WAIT0() asm volatile("cp.async.wait_group 0;" ::: "memory")

// pack 8 floats -> hi uint4 and lo uint4 (lo = v - hi)
__device__ __forceinline__ void split8(const float* v, uint4& hi4, uint4& lo4) {
    __half2 h[4], l[4];
    #pragma unroll
    for (int i = 0; i < 4; i++) {
        h[i] = __floats2half2_rn(v[2 * i], v[2 * i + 1]);
        float2 hf = __half22float2(h[i]);
        l[i] = __floats2half2_rn(v[2 * i] - hf.x, v[2 * i + 1] - hf.y);
    }
    hi4.x = *reinterpret_cast<uint32_t*>(&h[0]);
    hi4.y = *reinterpret_cast<uint32_t*>(&h[1]);
    hi4.z = *reinterpret_cast<uint32_t*>(&h[2]);
    hi4.w = *reinterpret_cast<uint32_t*>(&h[3]);
    lo4.x = *reinterpret_cast<uint32_t*>(&l[0]);
    lo4.y = *reinterpret_cast<uint32_t*>(&l[1]);
    lo4.z = *reinterpret_cast<uint32_t*>(&l[2]);
    lo4.w = *reinterpret_cast<uint32_t*>(&l[3]);
}

// ---------------- init x = dec_input[:,0,:] ----------------
__global__ void copy_x_kernel(const float* __restrict__ dec) {
    int i = blockIdx.x * 256 + threadIdx.x;
    float v = dec[i];
    g_x[i] = v;
    int b = i >> 10, u = i & 1023;
    __half hi = __float2half_rn(v);
    g_inph[b * 2048 + u] = hi;
    g_inph[APLANE + b * 2048 + u] = __float2half_rn(v - __half2float(hi));
}

// ---------------- enc fp32 -> fp16 streaming ----------------
__global__ void ench_kernel(const float* __restrict__ enc) {
    size_t i = ((size_t)blockIdx.x * 256 + threadIdx.x) * 8;
    float4 v0 = *(const float4*)(enc + i);
    float4 v1 = *(const float4*)(enc + i + 4);
    __half2 h0 = __floats2half2_rn(v0.x, v0.y);
    __half2 h1 = __floats2half2_rn(v0.z, v0.w);
    __half2 h2 = __floats2half2_rn(v1.x, v1.y);
    __half2 h3 = __floats2half2_rn(v1.z, v1.w);
    uint4 u;
    u.x = *reinterpret_cast<uint32_t*>(&h0);
    u.y = *reinterpret_cast<uint32_t*>(&h1);
    u.z = *reinterpret_cast<uint32_t*>(&h2);
    u.w = *reinterpret_cast<uint32_t*>(&h3);
    *reinterpret_cast<uint4*>(g_ench + i) = u;
}

// ---------------- convert W1[k][n] -> g_W1h[n][k] fp16 ----------------
__global__ void conv_w1_kernel(const float* __restrict__ W1) {
    __shared__ float t[32][33];
    int n0 = blockIdx.x * 32, k0 = blockIdx.y * 32;
    int x = threadIdx.x, y = threadIdx.y;
    #pragma unroll
    for (int i = 0; i < 32; i += 8)
        t[y + i][x] = W1[(size_t)(k0 + y + i) * Un + n0 + x];
    __syncthreads();
    #pragma unroll
    for (int i = 0; i < 32; i += 8)
        g_W1h[(size_t)(n0 + y + i) * Un + k0 + x] = __float2half_rn(t[x][y + i]);
}

// ---------------- q2: 32-way k-split GEMM ----------------
__global__ __launch_bounds__(256) void q2_split_kernel(const float* __restrict__ qh,
                                                       const float* __restrict__ W2) {
    __shared__ float qs[32][68];
    const int tid = threadIdx.x;
    const int vt = blockIdx.x;
    const int ks = blockIdx.y;
    const int v = vt * 128 + (tid & 127);
    const int half = tid >> 7;
    const int k0 = ks * 32;

    for (int i = tid; i < 64 * 32; i += 256) {
        int b = i >> 5, k = i & 31;
        qs[k][b] = qh[b * Un + k0 + k];
    }
    __syncthreads();

    float acc[32];
    #pragma unroll
    for (int j = 0; j < 32; j++) acc[j] = 0.f;

    #pragma unroll 1
    for (int k = 0; k < 32; k++) {
        float w = W2[(size_t)(k0 + k) * Un + v];
        const float4* qrow = (const float4*)&qs[k][half * 32];
        #pragma unroll
        for (int j4 = 0; j4 < 8; j4++) {
            float4 q = qrow[j4];
            acc[j4 * 4 + 0] += w * q.x;
            acc[j4 * 4 + 1] += w * q.y;
            acc[j4 * 4 + 2] += w * q.z;
            acc[j4 * 4 + 3] += w * q.w;
        }
    }
    #pragma unroll
    for (int j = 0; j < 32; j++)
        g_q2p[ks][half * 32 + j][v] = acc[j];
}

__global__ void q2_fin_kernel(const float* __restrict__ b1, const float* __restrict__ b2) {
    int i = blockIdx.x * 256 + threadIdx.x;
    int b = i >> 10, v = i & 1023;
    float s = b1[v] + b2[v];
    #pragma unroll
    for (int ks = 0; ks < 32; ks++) s += g_q2p[ks][b][v];
    g_q2[i] = s;
}

// ========== HMMA fused score GEMM v4 (M=128, 512 thr, 3-stage pipe, 1 sync/iter) ==========
// stage s @ s*49152: A (128x64k fp16, 16KB) @+0, B (256n x 64k, 32KB) @+16384
#define SC_STG 49152
#define SCOFF_Q2 147456
#define SCOFF_AV 151552
#define SCOFF_RED 155648   // 512 floats
#define SC_SMEM 157696

__global__ __launch_bounds__(512, 1)
void score_mma_kernel(const float* __restrict__ attnV, const float* __restrict__ attnbV) {
    extern __shared__ char smem[];
    const uint32_t sb = smem_u32(smem);
    const int tid = threadIdx.x;
    const int lane = tid & 31;
    const int wid = tid >> 5;
    const int wm = wid & 3;      // rows wm*32..+32
    const int wn = wid >> 2;     // cols wn*64..+64 of 256-tile
    const int b = blockIdx.y;
    const int s0 = blockIdx.x * 128;

    float* q2s = (float*)(smem + SCOFF_Q2);
    float* avs = (float*)(smem + SCOFF_AV);
    float* red = (float*)(smem + SCOFF_RED);

    for (int i = tid; i < Un; i += 512) {
        q2s[i] = g_q2[b * Un + i];
        avs[i] = attnV[i];
    }

    const __half* panel = g_ench + ((size_t)b * Sn + s0) * Un;

    // A stage loader: 128 rows x 64k = 1024 chunks, 2/thread
    auto loadA = [&](int kk, int buf) {
        #pragma unroll
        for (int h = 0; h < 2; h++) {
            int id = h * 512 + tid;
            int r = id >> 3;
            int c = id & 7;
            cp16(sb + buf * SC_STG + r * 128 + ((c ^ (r & 7)) << 4),
                 panel + (size_t)r * Un + kk * 64 + c * 8);
        }
    };
    // B stage loader: 256n x 64k = 2048 chunks, 4/thread
    auto loadB = [&](int nt, int kk, int buf) {
        #pragma unroll
        for (int h = 0; h < 4; h++) {
            int ch = h * 512 + tid;
            int n = ch >> 3;
            int ck = ch & 7;
            cp16(sb + buf * SC_STG + 16384 + n * 128 + ((ck ^ (n & 7)) << 4),
                 g_W1h + (size_t)(nt * 256 + n) * Un + kk * 64 + ck * 8);
        }
    };

    // A ldsm bases: two 16-row tiles per warp
    const int ahi = lane >> 4;
    const int arow0 = wm * 32 + (lane & 15);
    const int arow1 = arow0 + 16;
    const uint32_t ao0 = arow0 * 128;
    const uint32_t ao1 = arow1 * 128;
    const int ax0 = arow0 & 7, ax1 = arow1 & 7;

    // B ldsm bases (4 col-tiles of 16)
    const int bhi = lane >> 4;
    uint32_t bno[4];
    int bxr[4];
    #pragma unroll
    for (int bt = 0; bt < 4; bt++) {
        int bn = wn * 64 + bt * 16 + (lane & 15);
        bno[bt] = bn * 128;
        bxr[bt] = bn & 7;
    }

    const int g = lane >> 2;
    const int t = lane & 3;
    float pa[4];
    #pragma unroll
    for (int i = 0; i < 4; i++) pa[i] = 0.f;

    float dacc[16][4];

    // prologue: stages for idx 0, 1
    loadA(0, 0); loadB(0, 0, 0); CP_COMMIT();
    loadA(1, 1); loadB(0, 1, 1); CP_COMMIT();

    #pragma unroll 1
    for (int idx = 0; idx < 64; idx++) {
        const int nt = idx >> 4;
        const int kk = idx & 15;
        const int buf = idx % 3;
        if (kk == 0) {
            #pragma unroll
            for (int i = 0; i < 16; i++)
                #pragma unroll
                for (int j = 0; j < 4; j++) dacc[i][j] = 0.f;
        }
        if (idx < 63) { CP_WAIT1(); } else { CP_WAIT0(); }
        __syncthreads();
        if (idx < 62) {
            int n = idx + 2;
            loadA(n & 15, n % 3);
            loadB(n >> 4, n & 15, n % 3);
            CP_COMMIT();
        }
        const uint32_t ast = sb + buf * SC_STG;
        const uint32_t bst = ast + 16384;
        #pragma unroll
        for (int kk2 = 0; kk2 < 4; kk2++) {
            uint32_t a0[4], a1[4];
            const int ck = kk2 * 2;
            LDSM4(a0[0], a0[1], a0[2], a0[3], ast + ao0 + (((ck + ahi) ^ ax0) << 4));
            LDSM4(a1[0], a1[1], a1[2], a1[3], ast + ao1 + (((ck + ahi) ^ ax1) << 4));
            const int bck = ck + bhi;
            #pragma unroll
            for (int bt = 0; bt < 4; bt++) {
                uint32_t q[4];
                LDSM4(q[0], q[1], q[2], q[3], bst + bno[bt] + ((bck ^ bxr[bt]) << 4));
                mma16816(dacc[0 + bt * 2 + 0], a0, q[0], q[2]);
                mma16816(dacc[0 + bt * 2 + 1], a0, q[1], q[3]);
                mma16816(dacc[8 + bt * 2 + 0], a1, q[0], q[2]);
                mma16816(dacc[8 + bt * 2 + 1], a1, q[1], q[3]);
            }
        }
        if (kk == 15) {
            // epilogue for this n-tile: tanh(D + q2) * attnV
            #pragma unroll
            for (int at = 0; at < 2; at++)
                #pragma unroll
                for (int bt = 0; bt < 4; bt++)
                    #pragma unroll
                    for (int h = 0; h < 2; h++) {
                        const float* dd = dacc[at * 8 + bt * 2 + h];
                        int c0 = nt * 256 + wn * 64 + bt * 16 + h * 8 + 2 * t;
                        float qa = q2s[c0], qb = q2s[c0 + 1];
                        float va = avs[c0], vb = avs[c0 + 1];
                        pa[at * 2 + 0] += tanh_fast(dd[0] + qa) * va + tanh_fast(dd[1] + qb) * vb;
                        pa[at * 2 + 1] += tanh_fast(dd[2] + qa) * va + tanh_fast(dd[3] + qb) * vb;
                    }
        }
    }
    #pragma unroll
    for (int i = 0; i < 4; i++) {
        pa[i] += __shfl_xor_sync(0xffffffffu, pa[i], 1);
        pa[i] += __shfl_xor_sync(0xffffffffu, pa[i], 2);
    }
    if (t == 0) {
        #pragma unroll
        for (int at = 0; at < 2; at++)
            #pragma unroll
            for (int hh = 0; hh < 2; hh++)
                red[wn * 128 + wm * 32 + at * 16 + hh * 8 + g] = pa[at * 2 + hh];
    }
    __syncthreads();
    if (tid < 128) {
        g_score[b * Sn + s0 + tid] =
            red[tid] + red[128 + tid] + red[256 + tid] + red[384 + tid] + attnbV[0];
    }
}

// ---------------- softmax over S ----------------
__global__ void softmax_s_kernel(float* __restrict__ out_attnw) {
    int b = blockIdx.x;
    int tid = threadIdx.x;
    __shared__ float red[256];
    float m = -1e30f;
    for (int s = tid; s < Sn; s += 256) m = fmaxf(m, g_score[b * Sn + s]);
    red[tid] = m; __syncthreads();
    for (int o = 128; o > 0; o >>= 1) { if (tid < o) red[tid] = fmaxf(red[tid], red[tid + o]); __syncthreads(); }
    m = red[0]; __syncthreads();
    float sum = 0.f;
    for (int s = tid; s < Sn; s += 256) {
        float e = expf(g_score[b * Sn + s] - m);
        g_attnw[b * Sn + s] = e;
        sum += e;
    }
    red[tid] = sum; __syncthreads();
    for (int o = 128; o > 0; o >>= 1) { if (tid < o) red[tid] += red[tid + o]; __syncthreads(); }
    float inv = 1.f / red[0];
    for (int s = tid; s < Sn; s += 256) {
        float w = g_attnw[b * Sn + s] * inv;
        g_attnw[b * Sn + s] = w;
        out_attnw[b * Sn + s] = w;
    }
}

// ---------------- ctx partials: 8 s-splits, half2 loads ----------------
__global__ void ctx_part_kernel() {
    int b = blockIdx.x;
    int u0 = (blockIdx.y * 128 + threadIdx.x) * 2;
    int ss = blockIdx.z;
    const __half2* e = (const __half2*)(g_ench + (size_t)b * Sn * Un +
                                        (size_t)(ss * 256) * Un + u0);
    const float* w = g_attnw + b * Sn + ss * 256;
    float ax = 0.f, ay = 0.f;
    #pragma unroll 4
    for (int s = 0; s < 256; s++) {
        float2 v = __half22float2(e[(size_t)s * (Un / 2)]);
        float ws = w[s];
        ax += ws * v.x;
        ay += ws * v.y;
    }
    g_ctxp[ss][b][u0] = ax;
    g_ctxp[ss][b][u0 + 1] = ay;
}

__global__ void ctx_fin_kernel() {
    int i = blockIdx.x * 256 + threadIdx.x;
    int b = i >> 10, u = i & 1023;
    float c = 0.f;
    #pragma unroll
    for (int ss = 0; ss < 8; ss++) c += g_ctxp[ss][b][u];
    __half hi = __float2half_rn(c);
    g_inph[b * 2048 + 1024 + u] = hi;
    g_inph[APLANE + b * 2048 + 1024 + u] = __float2half_rn(c - __half2float(hi));
}

// =================== LSTM GEMM: 16-way k-split pipelined split-fp16 HMMA ===================
__global__ __launch_bounds__(128)
void lstm_mma_kernel(const float* __restrict__ W) {
    __shared__ __align__(128) char sm[65536];
    const uint32_t sb = smem_u32(sm);
    const int tid = threadIdx.x, lane = tid & 31, wid = tid >> 5;
    const int wm = wid & 1, wn = wid >> 1;
    const int nt = blockIdx.x;
    const int ks = blockIdx.y;     // 16 splits of 128 k
    const int k0 = ks * 128;
    const int wcol0 = nt * 64 + (nt >= 16 ? 1024 : 0);
    const int zcol0 = nt * 64;

    float dacc[8][4];
    #pragma unroll
    for (int i = 0; i < 8; i++)
        #pragma unroll
        for (int j = 0; j < 4; j++) dacc[i][j] = 0.f;

    const int hi16 = lane >> 4;
    const int g8 = lane >> 3;
    const int r8 = lane & 7;
    const int arow0 = wm * 32 + (lane & 15);
    const int arow1 = arow0 + 16;

    auto loadW = [&](int kk, float* wv) {
        #pragma unroll
        for (int j = 0; j < 4; j++) {
            int ch = j * 128 + tid;
            int k = ch >> 3, c = ch & 7;
            const float* src = W + (size_t)(k0 + kk * 64 + k) * 4096 + wcol0 + c * 8;
            float4 s0 = *(const float4*)src;
            float4 s1 = *(const float4*)(src + 4);
            wv[j * 8 + 0] = s0.x; wv[j * 8 + 1] = s0.y; wv[j * 8 + 2] = s0.z; wv[j * 8 + 3] = s0.w;
            wv[j * 8 + 4] = s1.x; wv[j * 8 + 5] = s1.y; wv[j * 8 + 6] = s1.z; wv[j * 8 + 7] = s1.w;
        }
    };
    auto stsB = [&](const float* wv, int buf) {
        #pragma unroll
        for (int j = 0; j < 4; j++) {
            int ch = j * 128 + tid;
            int k = ch >> 3, c = ch & 7;
            uint4 hi4, lo4;
            split8(wv + j * 8, hi4, lo4);
            int off = 32768 + buf * 16384 + k * 128 + ((c ^ (k & 7)) << 4);
            *(uint4*)(sm + off) = hi4;
            *(uint4*)(sm + off + 8192) = lo4;
        }
    };
    auto cpA = [&](int kk, int st) {
        #pragma unroll
        for (int j = 0; j < 8; j++) {
            int ch = j * 128 + tid;
            int plane = ch >> 9, cc = ch & 511;
            int m = cc >> 3, c = cc & 7;
            cp16(sb + st * 16384 + plane * 8192 + m * 128 + ((c ^ (m & 7)) << 4),
                 g_inph + (size_t)plane * APLANE + (size_t)m * 2048 + k0 + kk * 64 + c * 8);
        }
    };

    float wv[32], wv2[32];
    loadW(0, wv);
    cpA(0, 0);
    CP_COMMIT();

    #pragma unroll 1
    for (int kk = 0; kk < 2; kk++) {
        const int buf = kk & 1;
        stsB(wv, buf);
        if (kk < 1) loadW(kk + 1, wv2);
        CP_WAIT0();
        __syncthreads();
        if (kk < 1) { cpA(kk + 1, buf ^ 1); CP_COMMIT(); }
        #pragma unroll
        for (int seg = 0; seg < 3; seg++) {
            const uint32_t abase = sb + buf * 16384 + (seg == 2 ? 8192 : 0);
            const uint32_t bbase = sb + 32768 + buf * 16384 + (seg == 1 ? 8192 : 0);
            #pragma unroll
            for (int kk2 = 0; kk2 < 4; kk2++) {
                uint32_t a0[4], a1[4];
                int ck = kk2 * 2 + hi16;
                LDSM4(a0[0], a0[1], a0[2], a0[3],
                      abase + arow0 * 128 + ((ck ^ (arow0 & 7)) << 4));
                LDSM4(a1[0], a1[1], a1[2], a1[3],
                      abase + arow1 * 128 + ((ck ^ (arow1 & 7)) << 4));
                int kloc = kk2 * 16 + (g8 & 1) * 8 + r8;
                #pragma unroll
                for (int bt = 0; bt < 2; bt++) {
                    int nchunk = wn * 4 + bt * 2 + (g8 >> 1);
                    uint32_t q[4];
                    LDSM4T(q[0], q[1], q[2], q[3],
                           bbase + kloc * 128 + ((nchunk ^ (kloc & 7)) << 4));
                    mma16816(dacc[0 + bt * 2 + 0], a0, q[0], q[1]);
                    mma16816(dacc[0 + bt * 2 + 1], a0, q[2], q[3]);
                    mma16816(dacc[4 + bt * 2 + 0], a1, q[0], q[1]);
                    mma16816(dacc[4 + bt * 2 + 1], a1, q[2], q[3]);
                }
            }
        }
        #pragma unroll
        for (int j = 0; j < 32; j++) wv[j] = wv2[j];
        __syncthreads();
    }
    const int g = lane >> 2;
    const int t = lane & 3;
    float* zp = g_zp16 + (size_t)ks * Bn * 3072;
    #pragma unroll
    for (int at = 0; at < 2; at++)
        #pragma unroll
        for (int bt = 0; bt < 2; bt++)
            #pragma unroll
            for (int h = 0; h < 2; h++) {
                const float* dd = dacc[at * 4 + bt * 2 + h];
                int c0 = zcol0 + wn * 32 + bt * 16 + h * 8 + 2 * t;
                int r0 = wm * 32 + at * 16 + g;
                zp[(size_t)r0 * 3072 + c0] = dd[0];
                zp[(size_t)r0 * 3072 + c0 + 1] = dd[1];
                zp[(size_t)(r0 + 8) * 3072 + c0] = dd[2];
                zp[(size_t)(r0 + 8) * 3072 + c0 + 1] = dd[3];
            }
}

// ---------------- LSTM activation: sum 16 partials ----------------
__global__ void lstm_act_kernel(const float* __restrict__ lb,
                                float* __restrict__ hs, float* __restrict__ cs,
                                int layer, int residual) {
    int b = blockIdx.x;
    int u = threadIdx.x;
    float zi = lb[u], zg = lb[2048 + u], zo = lb[3072 + u];
    #pragma unroll
    for (int ks = 0; ks < 16; ks++) {
        const float* zp = g_zp16 + ((size_t)ks * Bn + b) * 3072;
        zi += zp[u];
        zg += zp[1024 + u];
        zo += zp[2048 + u];
    }
    float c = (1.f / (1.f + expf(-zi))) * tanhf(zg);
    float h = (1.f / (1.f + expf(-zo))) * tanhf(c);
    size_t o = ((size_t)layer * Bn + b) * Un + u;
    hs[o] = h;
    cs[o] = c;
    float xo = g_x[b * Un + u];
    float xn = residual ? (h + xo) : h;
    g_x[b * Un + u] = xn;
    __half hhi = __float2half_rn(xn);
    g_inph[b * 2048 + u] = hhi;
    g_inph[APLANE + b * 2048 + u] = __float2half_rn(xn - __half2float(hhi));
}

// =================== dense GEMM: pipelined fused-conversion split-fp16 HMMA ===================
__global__ __launch_bounds__(128)
void dense_mma_kernel(const float* __restrict__ W, const float* __restrict__ db) {
    __shared__ __align__(128) char sm[65536];
    const uint32_t sb = smem_u32(sm);
    const int tid = threadIdx.x, lane = tid & 31, wid = tid >> 5;
    const int wm = wid & 1, wn = wid >> 1;
    const int n0 = blockIdx.x * 64;

    float dacc[8][4];
    #pragma unroll
    for (int i = 0; i < 8; i++)
        #pragma unroll
        for (int j = 0; j < 4; j++) dacc[i][j] = 0.f;

    const int hi16 = lane >> 4;
    const int g8 = lane >> 3;
    const int r8 = lane & 7;
    const int arow0 = wm * 32 + (lane & 15);
    const int arow1 = arow0 + 16;

    auto loadW = [&](int kk, float* wv) {
        #pragma unroll
        for (int j = 0; j < 4; j++) {
            int ch = j * 128 + tid;
            int k = ch >> 3, c = ch & 7;
            const float* src = W + (size_t)(kk * 64 + k) * Vn + n0 + c * 8;
            #pragma unroll
            for (int e = 0; e < 8; e++) {
                int ng = n0 + c * 8 + e;
                wv[j * 8 + e] = (ng < Vn) ? src[e] : 0.f;
            }
        }
    };
    auto stsB = [&](const float* wv, int buf) {
        #pragma unroll
        for (int j = 0; j < 4; j++) {
            int ch = j * 128 + tid;
            int k = ch >> 3, c = ch & 7;
            uint4 hi4, lo4;
            split8(wv + j * 8, hi4, lo4);
            int off = 32768 + buf * 16384 + k * 128 + ((c ^ (k & 7)) << 4);
            *(uint4*)(sm + off) = hi4;
            *(uint4*)(sm + off + 8192) = lo4;
        }
    };
    auto cpA = [&](int kk, int st) {
        #pragma unroll
        for (int j = 0; j < 8; j++) {
            int ch = j * 128 + tid;
            int plane = ch >> 9, cc = ch & 511;
            int m = cc >> 3, c = cc & 7;
            cp16(sb + st * 16384 + plane * 8192 + m * 128 + ((c ^ (m & 7)) << 4),
                 g_inph + (size_t)plane * APLANE + (size_t)m * 2048 + kk * 64 + c * 8);
        }
    };

    float wv[32], wv2[32];
    loadW(0, wv);
    cpA(0, 0);
    CP_COMMIT();

    #pragma unroll 1
    for (int kk = 0; kk < 16; kk++) {
        const int buf = kk & 1;
        stsB(wv, buf);
        if (kk < 15) loadW(kk + 1, wv2);
        CP_WAIT0();
        __syncthreads();
        if (kk < 15) { cpA(kk + 1, buf ^ 1); CP_COMMIT(); }
        #pragma unroll
        for (int seg = 0; seg < 3; seg++) {
            const uint32_t abase = sb + buf * 16384 + (seg == 2 ? 8192 : 0);
            const uint32_t bbase = sb + 32768 + buf * 16384 + (seg == 1 ? 8192 : 0);
            #pragma unroll
            for (int kk2 = 0; kk2 < 4; kk2++) {
                uint32_t a0[4], a1[4];
                int ck = kk2 * 2 + hi16;
                LDSM4(a0[0], a0[1], a0[2], a0[3],
                      abase + arow0 * 128 + ((ck ^ (arow0 & 7)) << 4));
                LDSM4(a1[0], a1[1], a1[2], a1[3],
                      abase + arow1 * 128 + ((ck ^ (arow1 & 7)) << 4));
                int kloc = kk2 * 16 + (g8 & 1) * 8 + r8;
                #pragma unroll
                for (int bt = 0; bt < 2; bt++) {
                    int nchunk = wn * 4 + bt * 2 + (g8 >> 1);
                    uint32_t q[4];
                    LDSM4T(q[0], q[1], q[2], q[3],
                           bbase + kloc * 128 + ((nchunk ^ (kloc & 7)) << 4));
                    mma16816(dacc[0 + bt * 2 + 0], a0, q[0], q[1]);
                    mma16816(dacc[0 + bt * 2 + 1], a0, q[2], q[3]);
                    mma16816(dacc[4 + bt * 2 + 0], a1, q[0], q[1]);
                    mma16816(dacc[4 + bt * 2 + 1], a1, q[2], q[3]);
                }
            }
        }
        #pragma unroll
        for (int j = 0; j < 32; j++) wv[j] = wv2[j];
        __syncthreads();
    }
    const int g = lane >> 2;
    const int t = lane & 3;
    #pragma unroll
    for (int at = 0; at < 2; at++)
        #pragma unroll
        for (int bt = 0; bt < 2; bt++)
            #pragma unroll
            for (int h = 0; h < 2; h++) {
                const float* dd = dacc[at * 4 + bt * 2 + h];
                int c0 = n0 + wn * 32 + bt * 16 + h * 8 + 2 * t;
                int r0 = wm * 32 + at * 16 + g;
                if (c0 < Vn) {
                    float bb = db[c0];
                    g_logits[(size_t)r0 * Vn + c0] = dd[0] + bb;
                    g_logits[(size_t)(r0 + 8) * Vn + c0] = dd[2] + bb;
                }
                if (c0 + 1 < Vn) {
                    float bb = db[c0 + 1];
                    g_logits[(size_t)r0 * Vn + c0 + 1] = dd[1] + bb;
                    g_logits[(size_t)(r0 + 8) * Vn + c0 + 1] = dd[3] + bb;
                }
            }
}

// ---------------- softmax over V -> probs ----------------
__global__ void softmax_v_kernel(float* __restrict__ probs) {
    int b = blockIdx.x;
    int tid = threadIdx.x;
    __shared__ float red[1024];
    const float* lg = g_logits + (size_t)b * Vn;
    float m = -1e30f;
    for (int j = tid; j < Vn; j += 1024) m = fmaxf(m, lg[j]);
    red[tid] = m; __syncthreads();
    for (int o = 512; o > 0; o >>= 1) { if (tid < o) red[tid] = fmaxf(red[tid], red[tid + o]); __syncthreads(); }
    m = red[0]; __syncthreads();
    float sum = 0.f;
    float* pb = probs + (size_t)b * Vn;
    for (int j = tid; j < Vn; j += 1024) {
        float e = expf(lg[j] - m);
        pb[j] = e;
        sum += e;
    }
    red[tid] = sum; __syncthreads();
    for (int o = 512; o > 0; o >>= 1) { if (tid < o) red[tid] += red[tid + o]; __syncthreads(); }
    float inv = 1.f / red[0];
    for (int j = tid; j < Vn; j += 1024) pb[j] *= inv;
}

// ---------------- launch ----------------
extern "C" void kernel_launch(void* const* d_in, const int* in_sizes, int n_in,
                              void* d_out, int out_size) {
    const float* enc = (const float*)d_in[0];
    const float* dec = (const float*)d_in[1];
    const float* qh  = (const float*)d_in[2];
    const float* W1  = (const float*)d_in[3];
    const float* b1  = (const float*)d_in[4];
    const float* W2  = (const float*)d_in[5];
    const float* b2  = (const float*)d_in[6];
    const float* aV  = (const float*)d_in[7];
    const float* abV = (const float*)d_in[8];
    const float* lW  = (const float*)d_in[9];
    const float* lb  = (const float*)d_in[10];
    const float* dW  = (const float*)d_in[11];
    const float* db  = (const float*)d_in[12];

    float* out   = (float*)d_out;
    float* probs = out;
    float* hs    = out + (size_t)Bn * Vn;
    float* cs    = hs + (size_t)Ln * Bn * Un;
    float* attnw = cs + (size_t)Ln * Bn * Un;

    static const int RES[8] = {0, 0, 1, 1, 1, 1, 1, 0};

    cudaFuncSetAttribute(score_mma_kernel,
                         cudaFuncAttributeMaxDynamicSharedMemorySize, SC_SMEM);

    copy_x_kernel<<<256, 256>>>(dec);
    ench_kernel<<<65536, 256>>>(enc);
    conv_w1_kernel<<<dim3(32, 32), dim3(32, 8)>>>(W1);
    q2_split_kernel<<<dim3(8, 32), 256>>>(qh, W2);
    q2_fin_kernel<<<256, 256>>>(b1, b2);
    score_mma_kernel<<<dim3(Sn / 128, Bn), 512, SC_SMEM>>>(aV, abV);
    softmax_s_kernel<<<Bn, 256>>>(attnw);
    ctx_part_kernel<<<dim3(Bn, 4, 8), 128>>>();
    ctx_fin_kernel<<<256, 256>>>();

    for (int l = 0; l < Ln; l++) {
        lstm_mma_kernel<<<dim3(48, 16), 128>>>(lW + (size_t)l * 2048 * 4096);
        lstm_act_kernel<<<Bn, 1024>>>(lb + (size_t)l * 4096, hs, cs, l, RES[l]);
    }

    dense_mma_kernel<<<VnP / 64, 128>>>(dW, db);
    softmax_v_kernel<<<Bn, 1024>>>(probs);
}

// round 14
// speedup vs baseline: 1.0062x; 1.0016x over previous
#include <cuda_runtime.h>
#include <cuda_fp16.h>
#include <math.h>
#include <stdint.h>

#define Bn 64
#define Sn 2048
#define Un 1024
#define Vn 50257
#define VnP 50304
#define Ln 8

// ---------------- scratch (device globals; no allocs allowed) ----------------
__device__ float g_q2[Bn * Un];
__device__ float g_q2p[64][Bn][Un];                    // q2 k-split partials
__device__ float g_ctxp[8][Bn][Un];                    // ctx s-split partials
__device__ float g_score[Bn * Sn];
__device__ float g_attnw[Bn * Sn];
__device__ float g_x[Bn * Un];
__device__ float g_zp8[8 * Bn * 3072];                 // lstm k-split partials (i|g|o)
__device__ float g_logits[(size_t)Bn * Vn];
__device__ float g_logitsP[2][(size_t)Bn * Vn];        // dense k-split partials
__device__ __half g_W1h[(size_t)Un * Un];              // W1^T [n][k] fp16
__device__ __half g_ench[(size_t)Bn * Sn * Un];        // enc as fp16
__device__ __half g_inph[2 * Bn * 2048];               // [plane][b][x|ctx] hi/lo

#define APLANE ((size_t)Bn * 2048)

// ======================= helpers =======================
__device__ __forceinline__ uint32_t smem_u32(const void* p) {
    uint32_t a;
    asm("{ .reg .u64 t; cvta.to.shared.u64 t, %1; cvt.u32.u64 %0, t; }" : "=r"(a) : "l"(p));
    return a;
}
__device__ __forceinline__ float tanh_fast(float x) {
    float y;
    asm("tanh.approx.f32 %0, %1;" : "=f"(y) : "f"(x));
    return y;
}
#define LDSM4(r0, r1, r2, r3, addr) \
    asm volatile("ldmatrix.sync.aligned.m8n8.x4.shared.b16 {%0,%1,%2,%3}, [%4];" \
                 : "=r"(r0), "=r"(r1), "=r"(r2), "=r"(r3) : "r"(addr))
#define LDSM4T(r0, r1, r2, r3, addr) \
    asm volatile("ldmatrix.sync.aligned.m8n8.x4.trans.shared.b16 {%0,%1,%2,%3}, [%4];" \
                 : "=r"(r0), "=r"(r1), "=r"(r2), "=r"(r3) : "r"(addr))
__device__ __forceinline__ void mma16816(float* d, const uint32_t* a, uint32_t b0, uint32_t b1) {
    asm volatile(
        "mma.sync.aligned.m16n8k16.row.col.f32.f16.f16.f32 "
        "{%0,%1,%2,%3}, {%4,%5,%6,%7}, {%8,%9}, {%0,%1,%2,%3};"
        : "+f"(d[0]), "+f"(d[1]), "+f"(d[2]), "+f"(d[3])
        : "r"(a[0]), "r"(a[1]), "r"(a[2]), "r"(a[3]), "r"(b0), "r"(b1));
}
__device__ __forceinline__ void cp16(uint32_t s, const void* g) {
    asm volatile("cp.async.ca.shared.global [%0], [%1], 16;" :: "r"(s), "l"(g));
}
#define CP_COMMIT() asm volatile("cp.async.commit_group;" ::: "memory")
#define CP_WAIT1() asm volatile("cp.async.wait_group 1;" ::: "memory")
#define CP_WAIT0() asm volatile("cp.async.wait_group 0;" ::: "memory")

// pack 8 floats -> hi uint4 and lo uint4 (lo = v - hi)
__device__ __forceinline__ void split8(const float* v, uint4& hi4, uint4& lo4) {
    __half2 h[4], l[4];
    #pragma unroll
    for (int i = 0; i < 4; i++) {
        h[i] = __floats2half2_rn(v[2 * i], v[2 * i + 1]);
        float2 hf = __half22float2(h[i]);
        l[i] = __floats2half2_rn(v[2 * i] - hf.x, v[2 * i + 1] - hf.y);
    }
    hi4.x = *reinterpret_cast<uint32_t*>(&h[0]);
    hi4.y = *reinterpret_cast<uint32_t*>(&h[1]);
    hi4.z = *reinterpret_cast<uint32_t*>(&h[2]);
    hi4.w = *reinterpret_cast<uint32_t*>(&h[3]);
    lo4.x = *reinterpret_cast<uint32_t*>(&l[0]);
    lo4.y = *reinterpret_cast<uint32_t*>(&l[1]);
    lo4.z = *reinterpret_cast<uint32_t*>(&l[2]);
    lo4.w = *reinterpret_cast<uint32_t*>(&l[3]);
}

// ---------------- init x = dec_input[:,0,:] ----------------
__global__ void copy_x_kernel(const float* __restrict__ dec) {
    int i = blockIdx.x * 256 + threadIdx.x;
    float v = dec[i];
    g_x[i] = v;
    int b = i >> 10, u = i & 1023;
    __half hi = __float2half_rn(v);
    g_inph[b * 2048 + u] = hi;
    g_inph[APLANE + b * 2048 + u] = __float2half_rn(v - __half2float(hi));
}

// ---------------- enc fp32 -> fp16 streaming ----------------
__global__ void ench_kernel(const float* __restrict__ enc) {
    size_t i = ((size_t)blockIdx.x * 256 + threadIdx.x) * 8;
    float4 v0 = *(const float4*)(enc + i);
    float4 v1 = *(const float4*)(enc + i + 4);
    __half2 h0 = __floats2half2_rn(v0.x, v0.y);
    __half2 h1 = __floats2half2_rn(v0.z, v0.w);
    __half2 h2 = __floats2half2_rn(v1.x, v1.y);
    __half2 h3 = __floats2half2_rn(v1.z, v1.w);
    uint4 u;
    u.x = *reinterpret_cast<uint32_t*>(&h0);
    u.y = *reinterpret_cast<uint32_t*>(&h1);
    u.z = *reinterpret_cast<uint32_t*>(&h2);
    u.w = *reinterpret_cast<uint32_t*>(&h3);
    *reinterpret_cast<uint4*>(g_ench + i) = u;
}

// ---------------- convert W1[k][n] -> g_W1h[n][k] fp16 ----------------
__global__ void conv_w1_kernel(const float* __restrict__ W1) {
    __shared__ float t[32][33];
    int n0 = blockIdx.x * 32, k0 = blockIdx.y * 32;
    int x = threadIdx.x, y = threadIdx.y;
    #pragma unroll
    for (int i = 0; i < 32; i += 8)
        t[y + i][x] = W1[(size_t)(k0 + y + i) * Un + n0 + x];
    __syncthreads();
    #pragma unroll
    for (int i = 0; i < 32; i += 8)
        g_W1h[(size_t)(n0 + y + i) * Un + k0 + x] = __float2half_rn(t[x][y + i]);
}

// ---------------- q2: 64-way k-split GEMM ----------------
__global__ __launch_bounds__(256) void q2_split_kernel(const float* __restrict__ qh,
                                                       const float* __restrict__ W2) {
    __shared__ float qs[16][68];
    const int tid = threadIdx.x;
    const int vt = blockIdx.x;      // 8 v-tiles of 128
    const int ks = blockIdx.y;      // 64 k-splits of 16
    const int v = vt * 128 + (tid & 127);
    const int half = tid >> 7;
    const int k0 = ks * 16;

    for (int i = tid; i < 64 * 16; i += 256) {
        int b = i >> 4, k = i & 15;
        qs[k][b] = qh[b * Un + k0 + k];
    }
    __syncthreads();

    float acc[32];
    #pragma unroll
    for (int j = 0; j < 32; j++) acc[j] = 0.f;

    #pragma unroll 1
    for (int k = 0; k < 16; k++) {
        float w = W2[(size_t)(k0 + k) * Un + v];
        const float4* qrow = (const float4*)&qs[k][half * 32];
        #pragma unroll
        for (int j4 = 0; j4 < 8; j4++) {
            float4 q = qrow[j4];
            acc[j4 * 4 + 0] += w * q.x;
            acc[j4 * 4 + 1] += w * q.y;
            acc[j4 * 4 + 2] += w * q.z;
            acc[j4 * 4 + 3] += w * q.w;
        }
    }
    #pragma unroll
    for (int j = 0; j < 32; j++)
        g_q2p[ks][half * 32 + j][v] = acc[j];
}

__global__ void q2_fin_kernel(const float* __restrict__ b1, const float* __restrict__ b2) {
    int i = blockIdx.x * 256 + threadIdx.x;
    int b = i >> 10, v = i & 1023;
    float s = b1[v] + b2[v];
    #pragma unroll
    for (int ks = 0; ks < 64; ks++) s += g_q2p[ks][b][v];
    g_q2[i] = s;
}

// ========== HMMA fused score GEMM (M=128, 512 threads, 16 warps 4m x 4n, 2-stage) ==========
#define SCOFF_Q2 98304
#define SCOFF_AV 102400
#define SCOFF_RED 106496   // 512 floats
#define SC_SMEM 108544

__global__ __launch_bounds__(512, 1)
void score_mma_kernel(const float* __restrict__ attnV, const float* __restrict__ attnbV) {
    extern __shared__ char smem[];
    const uint32_t sb = smem_u32(smem);
    const int tid = threadIdx.x;
    const int lane = tid & 31;
    const int wid = tid >> 5;
    const int wm = wid & 3;      // rows wm*32..+32
    const int wn = wid >> 2;     // cols wn*64..+64 of 256-tile
    const int b = blockIdx.y;
    const int s0 = blockIdx.x * 128;

    float* q2s = (float*)(smem + SCOFF_Q2);
    float* avs = (float*)(smem + SCOFF_AV);
    float* red = (float*)(smem + SCOFF_RED);

    for (int i = tid; i < Un; i += 512) {
        q2s[i] = g_q2[b * Un + i];
        avs[i] = attnV[i];
    }

    const __half* panel = g_ench + ((size_t)b * Sn + s0) * Un;

    // A stage loader: 128 rows x 64k = 1024 chunks, 2/thread
    auto loadA = [&](int kk, int buf) {
        #pragma unroll
        for (int h = 0; h < 2; h++) {
            int id = h * 512 + tid;
            int r = id >> 3;
            int c = id & 7;
            cp16(sb + buf * 16384 + r * 128 + ((c ^ (r & 7)) << 4),
                 panel + (size_t)r * Un + kk * 64 + c * 8);
        }
    };
    // B stage loader: 256n x 64k = 2048 chunks, 4/thread
    auto loadB = [&](int nt, int kk, int buf) {
        #pragma unroll
        for (int h = 0; h < 4; h++) {
            int ch = h * 512 + tid;
            int n = ch >> 3;
            int ck = ch & 7;
            cp16(sb + 32768 + buf * 32768 + n * 128 + ((ck ^ (n & 7)) << 4),
                 g_W1h + (size_t)(nt * 256 + n) * Un + kk * 64 + ck * 8);
        }
    };

    // A ldsm bases: two 16-row tiles per warp
    const int ahi = lane >> 4;
    const int arow0 = wm * 32 + (lane & 15);
    const int arow1 = arow0 + 16;
    const uint32_t ao0 = arow0 * 128;
    const uint32_t ao1 = arow1 * 128;
    const int ax0 = arow0 & 7, ax1 = arow1 & 7;

    // B ldsm bases (4 col-tiles of 16)
    const int bhi = lane >> 4;
    uint32_t bno[4];
    int bxr[4];
    #pragma unroll
    for (int bt = 0; bt < 4; bt++) {
        int bn = wn * 64 + bt * 16 + (lane & 15);
        bno[bt] = bn * 128;
        bxr[bt] = bn & 7;
    }

    const int g = lane >> 2;
    const int t = lane & 3;
    float pa[4];
    #pragma unroll
    for (int i = 0; i < 4; i++) pa[i] = 0.f;

    float dacc[16][4];

    loadA(0, 0);
    loadB(0, 0, 0);
    CP_COMMIT();

    #pragma unroll 1
    for (int idx = 0; idx < 64; idx++) {
        const int nt = idx >> 4;
        const int kk = idx & 15;
        const int buf = idx & 1;
        if (kk == 0) {
            #pragma unroll
            for (int i = 0; i < 16; i++)
                #pragma unroll
                for (int j = 0; j < 4; j++) dacc[i][j] = 0.f;
        }
        if (idx < 63) {
            int nidx = idx + 1;
            loadA(nidx & 15, nidx & 1);
            loadB(nidx >> 4, nidx & 15, nidx & 1);
            CP_COMMIT();
            CP_WAIT1();
        } else {
            CP_WAIT0();
        }
        __syncthreads();
        const uint32_t ast = sb + buf * 16384;
        const uint32_t bst = sb + 32768 + buf * 32768;
        #pragma unroll
        for (int kk2 = 0; kk2 < 4; kk2++) {
            uint32_t a0[4], a1[4];
            const int ck = kk2 * 2;
            LDSM4(a0[0], a0[1], a0[2], a0[3], ast + ao0 + (((ck + ahi) ^ ax0) << 4));
            LDSM4(a1[0], a1[1], a1[2], a1[3], ast + ao1 + (((ck + ahi) ^ ax1) << 4));
            const int bck = ck + bhi;
            #pragma unroll
            for (int bt = 0; bt < 4; bt++) {
                uint32_t q[4];
                LDSM4(q[0], q[1], q[2], q[3], bst + bno[bt] + ((bck ^ bxr[bt]) << 4));
                mma16816(dacc[0 + bt * 2 + 0], a0, q[0], q[2]);
                mma16816(dacc[0 + bt * 2 + 1], a0, q[1], q[3]);
                mma16816(dacc[8 + bt * 2 + 0], a1, q[0], q[2]);
                mma16816(dacc[8 + bt * 2 + 1], a1, q[1], q[3]);
            }
        }
        __syncthreads();
        if (kk == 15) {
            // epilogue for this n-tile: tanh(D + q2) * attnV
            #pragma unroll
            for (int at = 0; at < 2; at++)
                #pragma unroll
                for (int bt = 0; bt < 4; bt++)
                    #pragma unroll
                    for (int h = 0; h < 2; h++) {
                        const float* dd = dacc[at * 8 + bt * 2 + h];
                        int c0 = nt * 256 + wn * 64 + bt * 16 + h * 8 + 2 * t;
                        float qa = q2s[c0], qb = q2s[c0 + 1];
                        float va = avs[c0], vb = avs[c0 + 1];
                        pa[at * 2 + 0] += tanh_fast(dd[0] + qa) * va + tanh_fast(dd[1] + qb) * vb;
                        pa[at * 2 + 1] += tanh_fast(dd[2] + qa) * va + tanh_fast(dd[3] + qb) * vb;
                    }
        }
    }
    #pragma unroll
    for (int i = 0; i < 4; i++) {
        pa[i] += __shfl_xor_sync(0xffffffffu, pa[i], 1);
        pa[i] += __shfl_xor_sync(0xffffffffu, pa[i], 2);
    }
    if (t == 0) {
        #pragma unroll
        for (int at = 0; at < 2; at++)
            #pragma unroll
            for (int hh = 0; hh < 2; hh++)
                red[wn * 128 + wm * 32 + at * 16 + hh * 8 + g] = pa[at * 2 + hh];
    }
    __syncthreads();
    if (tid < 128) {
        g_score[b * Sn + s0 + tid] =
            red[tid] + red[128 + tid] + red[256 + tid] + red[384 + tid] + attnbV[0];
    }
}

// ---------------- softmax over S ----------------
__global__ void softmax_s_kernel(float* __restrict__ out_attnw) {
    int b = blockIdx.x;
    int tid = threadIdx.x;
    __shared__ float red[256];
    float m = -1e30f;
    for (int s = tid; s < Sn; s += 256) m = fmaxf(m, g_score[b * Sn + s]);
    red[tid] = m; __syncthreads();
    for (int o = 128; o > 0; o >>= 1) { if (tid < o) red[tid] = fmaxf(red[tid], red[tid + o]); __syncthreads(); }
    m = red[0]; __syncthreads();
    float sum = 0.f;
    for (int s = tid; s < Sn; s += 256) {
        float e = expf(g_score[b * Sn + s] - m);
        g_attnw[b * Sn + s] = e;
        sum += e;
    }
    red[tid] = sum; __syncthreads();
    for (int o = 128; o > 0; o >>= 1) { if (tid < o) red[tid] += red[tid + o]; __syncthreads(); }
    float inv = 1.f / red[0];
    for (int s = tid; s < Sn; s += 256) {
        float w = g_attnw[b * Sn + s] * inv;
        g_attnw[b * Sn + s] = w;
        out_attnw[b * Sn + s] = w;
    }
}

// ---------------- ctx partials: 8 s-splits, half2 loads ----------------
__global__ void ctx_part_kernel() {
    int b = blockIdx.x;
    int u0 = (blockIdx.y * 128 + threadIdx.x) * 2;
    int ss = blockIdx.z;
    const __half2* e = (const __half2*)(g_ench + (size_t)b * Sn * Un +
                                        (size_t)(ss * 256) * Un + u0);
    const float* w = g_attnw + b * Sn + ss * 256;
    float ax = 0.f, ay = 0.f;
    #pragma unroll 4
    for (int s = 0; s < 256; s++) {
        float2 v = __half22float2(e[(size_t)s * (Un / 2)]);
        float ws = w[s];
        ax += ws * v.x;
        ay += ws * v.y;
    }
    g_ctxp[ss][b][u0] = ax;
    g_ctxp[ss][b][u0 + 1] = ay;
}

__global__ void ctx_fin_kernel() {
    int i = blockIdx.x * 256 + threadIdx.x;
    int b = i >> 10, u = i & 1023;
    float c = 0.f;
    #pragma unroll
    for (int ss = 0; ss < 8; ss++) c += g_ctxp[ss][b][u];
    __half hi = __float2half_rn(c);
    g_inph[b * 2048 + 1024 + u] = hi;
    g_inph[APLANE + b * 2048 + 1024 + u] = __float2half_rn(c - __half2float(hi));
}

// =================== LSTM GEMM: 8-way k-split pipelined split-fp16 HMMA ===================
__global__ __launch_bounds__(128)
void lstm_mma_kernel(const float* __restrict__ W) {
    __shared__ __align__(128) char sm[65536];
    const uint32_t sb = smem_u32(sm);
    const int tid = threadIdx.x, lane = tid & 31, wid = tid >> 5;
    const int wm = wid & 1, wn = wid >> 1;
    const int nt = blockIdx.x;
    const int ks = blockIdx.y;
    const int k0 = ks * 256;
    const int wcol0 = nt * 64 + (nt >= 16 ? 1024 : 0);
    const int zcol0 = nt * 64;

    float dacc[8][4];
    #pragma unroll
    for (int i = 0; i < 8; i++)
        #pragma unroll
        for (int j = 0; j < 4; j++) dacc[i][j] = 0.f;

    const int hi16 = lane >> 4;
    const int g8 = lane >> 3;
    const int r8 = lane & 7;
    const int arow0 = wm * 32 + (lane & 15);
    const int arow1 = arow0 + 16;

    auto loadW = [&](int kk, float* wv) {
        #pragma unroll
        for (int j = 0; j < 4; j++) {
            int ch = j * 128 + tid;
            int k = ch >> 3, c = ch & 7;
            const float* src = W + (size_t)(k0 + kk * 64 + k) * 4096 + wcol0 + c * 8;
            float4 s0 = *(const float4*)src;
            float4 s1 = *(const float4*)(src + 4);
            wv[j * 8 + 0] = s0.x; wv[j * 8 + 1] = s0.y; wv[j * 8 + 2] = s0.z; wv[j * 8 + 3] = s0.w;
            wv[j * 8 + 4] = s1.x; wv[j * 8 + 5] = s1.y; wv[j * 8 + 6] = s1.z; wv[j * 8 + 7] = s1.w;
        }
    };
    auto stsB = [&](const float* wv, int buf) {
        #pragma unroll
        for (int j = 0; j < 4; j++) {
            int ch = j * 128 + tid;
            int k = ch >> 3, c = ch & 7;
            uint4 hi4, lo4;
            split8(wv + j * 8, hi4, lo4);
            int off = 32768 + buf * 16384 + k * 128 + ((c ^ (k & 7)) << 4);
            *(uint4*)(sm + off) = hi4;
            *(uint4*)(sm + off + 8192) = lo4;
        }
    };
    auto cpA = [&](int kk, int st) {
        #pragma unroll
        for (int j = 0; j < 8; j++) {
            int ch = j * 128 + tid;
            int plane = ch >> 9, cc = ch & 511;
            int m = cc >> 3, c = cc & 7;
            cp16(sb + st * 16384 + plane * 8192 + m * 128 + ((c ^ (m & 7)) << 4),
                 g_inph + (size_t)plane * APLANE + (size_t)m * 2048 + k0 + kk * 64 + c * 8);
        }
    };

    float wv[32], wv2[32];
    loadW(0, wv);
    cpA(0, 0);
    CP_COMMIT();

    #pragma unroll 1
    for (int kk = 0; kk < 4; kk++) {
        const int buf = kk & 1;
        stsB(wv, buf);
        if (kk < 3) loadW(kk + 1, wv2);
        CP_WAIT0();
        __syncthreads();
        if (kk < 3) { cpA(kk + 1, buf ^ 1); CP_COMMIT(); }
        #pragma unroll
        for (int seg = 0; seg < 3; seg++) {
            const uint32_t abase = sb + buf * 16384 + (seg == 2 ? 8192 : 0);
            const uint32_t bbase = sb + 32768 + buf * 16384 + (seg == 1 ? 8192 : 0);
            #pragma unroll
            for (int kk2 = 0; kk2 < 4; kk2++) {
                uint32_t a0[4], a1[4];
                int ck = kk2 * 2 + hi16;
                LDSM4(a0[0], a0[1], a0[2], a0[3],
                      abase + arow0 * 128 + ((ck ^ (arow0 & 7)) << 4));
                LDSM4(a1[0], a1[1], a1[2], a1[3],
                      abase + arow1 * 128 + ((ck ^ (arow1 & 7)) << 4));
                int kloc = kk2 * 16 + (g8 & 1) * 8 + r8;
                #pragma unroll
                for (int bt = 0; bt < 2; bt++) {
                    int nchunk = wn * 4 + bt * 2 + (g8 >> 1);
                    uint32_t q[4];
                    LDSM4T(q[0], q[1], q[2], q[3],
                           bbase + kloc * 128 + ((nchunk ^ (kloc & 7)) << 4));
                    mma16816(dacc[0 + bt * 2 + 0], a0, q[0], q[1]);
                    mma16816(dacc[0 + bt * 2 + 1], a0, q[2], q[3]);
                    mma16816(dacc[4 + bt * 2 + 0], a1, q[0], q[1]);
                    mma16816(dacc[4 + bt * 2 + 1], a1, q[2], q[3]);
                }
            }
        }
        #pragma unroll
        for (int j = 0; j < 32; j++) wv[j] = wv2[j];
        __syncthreads();
    }
    const int g = lane >> 2;
    const int t = lane & 3;
    float* zp = g_zp8 + (size_t)ks * Bn * 3072;
    #pragma unroll
    for (int at = 0; at < 2; at++)
        #pragma unroll
        for (int bt = 0; bt < 2; bt++)
            #pragma unroll
            for (int h = 0; h < 2; h++) {
                const float* dd = dacc[at * 4 + bt * 2 + h];
                int c0 = zcol0 + wn * 32 + bt * 16 + h * 8 + 2 * t;
                int r0 = wm * 32 + at * 16 + g;
                zp[(size_t)r0 * 3072 + c0] = dd[0];
                zp[(size_t)r0 * 3072 + c0 + 1] = dd[1];
                zp[(size_t)(r0 + 8) * 3072 + c0] = dd[2];
                zp[(size_t)(r0 + 8) * 3072 + c0 + 1] = dd[3];
            }
}

// ---------------- LSTM activation: sum 8 partials ----------------
__global__ void lstm_act_kernel(const float* __restrict__ lb,
                                float* __restrict__ hs, float* __restrict__ cs,
                                int layer, int residual) {
    int b = blockIdx.x;
    int u = threadIdx.x;
    float zi = lb[u], zg = lb[2048 + u], zo = lb[3072 + u];
    #pragma unroll
    for (int ks = 0; ks < 8; ks++) {
        const float* zp = g_zp8 + ((size_t)ks * Bn + b) * 3072;
        zi += zp[u];
        zg += zp[1024 + u];
        zo += zp[2048 + u];
    }
    float c = (1.f / (1.f + expf(-zi))) * tanhf(zg);
    float h = (1.f / (1.f + expf(-zo))) * tanhf(c);
    size_t o = ((size_t)layer * Bn + b) * Un + u;
    hs[o] = h;
    cs[o] = c;
    float xo = g_x[b * Un + u];
    float xn = residual ? (h + xo) : h;
    g_x[b * Un + u] = xn;
    __half hhi = __float2half_rn(xn);
    g_inph[b * 2048 + u] = hhi;
    g_inph[APLANE + b * 2048 + u] = __float2half_rn(xn - __half2float(hhi));
}

// =================== dense GEMM: 2-way k-split pipelined split-fp16 HMMA ===================
__global__ __launch_bounds__(128)
void dense_mma_kernel(const float* __restrict__ W) {
    __shared__ __align__(128) char sm[65536];
    const uint32_t sb = smem_u32(sm);
    const int tid = threadIdx.x, lane = tid & 31, wid = tid >> 5;
    const int wm = wid & 1, wn = wid >> 1;
    const int n0 = blockIdx.x * 64;
    const int ks = blockIdx.y;       // 2 k-splits of 512
    const int kbase = ks * 8;        // in 64-chunks

    float dacc[8][4];
    #pragma unroll
    for (int i = 0; i < 8; i++)
        #pragma unroll
        for (int j = 0; j < 4; j++) dacc[i][j] = 0.f;

    const int hi16 = lane >> 4;
    const int g8 = lane >> 3;
    const int r8 = lane & 7;
    const int arow0 = wm * 32 + (lane & 15);
    const int arow1 = arow0 + 16;

    auto loadW = [&](int kk, float* wv) {
        #pragma unroll
        for (int j = 0; j < 4; j++) {
            int ch = j * 128 + tid;
            int k = ch >> 3, c = ch & 7;
            const float* src = W + (size_t)((kbase + kk) * 64 + k) * Vn + n0 + c * 8;
            #pragma unroll
            for (int e = 0; e < 8; e++) {
                int ng = n0 + c * 8 + e;
                wv[j * 8 + e] = (ng < Vn) ? src[e] : 0.f;
            }
        }
    };
    auto stsB = [&](const float* wv, int buf) {
        #pragma unroll
        for (int j = 0; j < 4; j++) {
            int ch = j * 128 + tid;
            int k = ch >> 3, c = ch & 7;
            uint4 hi4, lo4;
            split8(wv + j * 8, hi4, lo4);
            int off = 32768 + buf * 16384 + k * 128 + ((c ^ (k & 7)) << 4);
            *(uint4*)(sm + off) = hi4;
            *(uint4*)(sm + off + 8192) = lo4;
        }
    };
    auto cpA = [&](int kk, int st) {
        #pragma unroll
        for (int j = 0; j < 8; j++) {
            int ch = j * 128 + tid;
            int plane = ch >> 9, cc = ch & 511;
            int m = cc >> 3, c = cc & 7;
            cp16(sb + st * 16384 + plane * 8192 + m * 128 + ((c ^ (m & 7)) << 4),
                 g_inph + (size_t)plane * APLANE + (size_t)m * 2048 + (kbase + kk) * 64 + c * 8);
        }
    };

    float wv[32], wv2[32];
    loadW(0, wv);
    cpA(0, 0);
    CP_COMMIT();

    #pragma unroll 1
    for (int kk = 0; kk < 8; kk++) {
        const int buf = kk & 1;
        stsB(wv, buf);
        if (kk < 7) loadW(kk + 1, wv2);
        CP_WAIT0();
        __syncthreads();
        if (kk < 7) { cpA(kk + 1, buf ^ 1); CP_COMMIT(); }
        #pragma unroll
        for (int seg = 0; seg < 3; seg++) {
            const uint32_t abase = sb + buf * 16384 + (seg == 2 ? 8192 : 0);
            const uint32_t bbase = sb + 32768 + buf * 16384 + (seg == 1 ? 8192 : 0);
            #pragma unroll
            for (int kk2 = 0; kk2 < 4; kk2++) {
                uint32_t a0[4], a1[4];
                int ck = kk2 * 2 + hi16;
                LDSM4(a0[0], a0[1], a0[2], a0[3],
                      abase + arow0 * 128 + ((ck ^ (arow0 & 7)) << 4));
                LDSM4(a1[0], a1[1], a1[2], a1[3],
                      abase + arow1 * 128 + ((ck ^ (arow1 & 7)) << 4));
                int kloc = kk2 * 16 + (g8 & 1) * 8 + r8;
                #pragma unroll
                for (int bt = 0; bt < 2; bt++) {
                    int nchunk = wn * 4 + bt * 2 + (g8 >> 1);
                    uint32_t q[4];
                    LDSM4T(q[0], q[1], q[2], q[3],
                           bbase + kloc * 128 + ((nchunk ^ (kloc & 7)) << 4));
                    mma16816(dacc[0 + bt * 2 + 0], a0, q[0], q[1]);
                    mma16816(dacc[0 + bt * 2 + 1], a0, q[2], q[3]);
                    mma16816(dacc[4 + bt * 2 + 0], a1, q[0], q[1]);
                    mma16816(dacc[4 + bt * 2 + 1], a1, q[2], q[3]);
                }
            }
        }
        #pragma unroll
        for (int j = 0; j < 32; j++) wv[j] = wv2[j];
        __syncthreads();
    }
    const int g = lane >> 2;
    const int t = lane & 3;
    float* lp = g_logitsP[ks];
    #pragma unroll
    for (int at = 0; at < 2; at++)
        #pragma unroll
        for (int bt = 0; bt < 2; bt++)
            #pragma unroll
            for (int h = 0; h < 2; h++) {
                const float* dd = dacc[at * 4 + bt * 2 + h];
                int c0 = n0 + wn * 32 + bt * 16 + h * 8 + 2 * t;
                int r0 = wm * 32 + at * 16 + g;
                if (c0 < Vn) {
                    lp[(size_t)r0 * Vn + c0] = dd[0];
                    lp[(size_t)(r0 + 8) * Vn + c0] = dd[2];
                }
                if (c0 + 1 < Vn) {
                    lp[(size_t)r0 * Vn + c0 + 1] = dd[1];
                    lp[(size_t)(r0 + 8) * Vn + c0 + 1] = dd[3];
                }
            }
}

// ---------------- softmax over V -> probs (sums dense partials + bias) ----------------
__global__ void softmax_v_kernel(float* __restrict__ probs, const float* __restrict__ db) {
    int b = blockIdx.x;
    int tid = threadIdx.x;
    __shared__ float red[1024];
    const float* l0 = g_logitsP[0] + (size_t)b * Vn;
    const float* l1 = g_logitsP[1] + (size_t)b * Vn;
    float* lg = g_logits + (size_t)b * Vn;
    float m = -1e30f;
    // pass 1: combine partials + bias, write lg, track max
    // (each thread writes and later reads the SAME j indices — no cross-thread hazard)
    for (int j = tid; j < Vn; j += 1024) {
        float v = l0[j] + l1[j] + db[j];
        lg[j] = v;
        m = fmaxf(m, v);
    }
    red[tid] = m; __syncthreads();
    for (int o = 512; o > 0; o >>= 1) { if (tid < o) red[tid] = fmaxf(red[tid], red[tid + o]); __syncthreads(); }
    m = red[0]; __syncthreads();
    float sum = 0.f;
    float* pb = probs + (size_t)b * Vn;
    for (int j = tid; j < Vn; j += 1024) {
        float e = expf(lg[j] - m);
        pb[j] = e;
        sum += e;
    }
    red[tid] = sum; __syncthreads();
    for (int o = 512; o > 0; o >>= 1) { if (tid < o) red[tid] += red[tid + o]; __syncthreads(); }
    float inv = 1.f / red[0];
    for (int j = tid; j < Vn; j += 1024) pb[j] *= inv;
}

// ---------------- launch ----------------
extern "C" void kernel_launch(void* const* d_in, const int* in_sizes, int n_in,
                              void* d_out, int out_size) {
    const float* enc = (const float*)d_in[0];
    const float* dec = (const float*)d_in[1];
    const float* qh  = (const float*)d_in[2];
    const float* W1  = (const float*)d_in[3];
    const float* b1  = (const float*)d_in[4];
    const float* W2  = (const float*)d_in[5];
    const float* b2  = (const float*)d_in[6];
    const float* aV  = (const float*)d_in[7];
    const float* abV = (const float*)d_in[8];
    const float* lW  = (const float*)d_in[9];
    const float* lb  = (const float*)d_in[10];
    const float* dW  = (const float*)d_in[11];
    const float* db  = (const float*)d_in[12];

    float* out   = (float*)d_out;
    float* probs = out;
    float* hs    = out + (size_t)Bn * Vn;
    float* cs    = hs + (size_t)Ln * Bn * Un;
    float* attnw = cs + (size_t)Ln * Bn * Un;

    static const int RES[8] = {0, 0, 1, 1, 1, 1, 1, 0};

    cudaFuncSetAttribute(score_mma_kernel,
                         cudaFuncAttributeMaxDynamicSharedMemorySize, SC_SMEM);

    copy_x_kernel<<<256, 256>>>(dec);
    ench_kernel<<<65536, 256>>>(enc);
    conv_w1_kernel<<<dim3(32, 32), dim3(32, 8)>>>(W1);
    q2_split_kernel<<<dim3(8, 64), 256>>>(qh, W2);
    q2_fin_kernel<<<256, 256>>>(b1, b2);
    score_mma_kernel<<<dim3(Sn / 128, Bn), 512, SC_SMEM>>>(aV, abV);
    softmax_s_kernel<<<Bn, 256>>>(attnw);
    ctx_part_kernel<<<dim3(Bn, 4, 8), 128>>>();
    ctx_fin_kernel<<<256, 256>>>();

    for (int l = 0; l < Ln; l++) {
        lstm_mma_kernel<<<dim3(48, 8), 128>>>(lW + (size_t)l * 2048 * 4096);
        lstm_act_kernel<<<Bn, 1024>>>(lb + (size_t)l * 4096, hs, cs, l, RES[l]);
    }

    dense_mma_kernel<<<dim3(VnP / 64, 2), 128>>>(dW);
    softmax_v_kernel<<<Bn, 1024>>>(probs, db);
}

// round 15
// speedup vs baseline: 1.0237x; 1.0174x over previous
#include <cuda_runtime.h>
#include <cuda_fp16.h>
#include <math.h>
#include <stdint.h>

#define Bn 64
#define Sn 2048
#define Un 1024
#define Vn 50257
#define VnP 50304
#define Ln 8

// ---------------- scratch (device globals; no allocs allowed) ----------------
__device__ float g_q2[Bn * Un];
__device__ float g_q2p[64][Bn][Un];                    // q2 k-split partials
__device__ float g_ctxp[8][Bn][Un];                    // ctx s-split partials
__device__ float g_score[Bn * Sn];
__device__ float g_attnw[Bn * Sn];
__device__ float g_x[Bn * Un];
__device__ float g_zp8[8 * Bn * 3072];                 // lstm k-split partials (i|g|o)
__device__ float g_logits[(size_t)Bn * Vn];
__device__ __half g_W1h[(size_t)Un * Un];              // W1^T [n][k] fp16
__device__ __half g_ench[(size_t)Bn * Sn * Un];        // enc as fp16
__device__ __half g_inph[2 * Bn * 2048];               // [plane][b][x|ctx] hi/lo

#define APLANE ((size_t)Bn * 2048)

// ======================= helpers =======================
__device__ __forceinline__ uint32_t smem_u32(const void* p) {
    uint32_t a;
    asm("{ .reg .u64 t; cvta.to.shared.u64 t, %1; cvt.u32.u64 %0, t; }" : "=r"(a) : "l"(p));
    return a;
}
__device__ __forceinline__ float tanh_fast(float x) {
    float y;
    asm("tanh.approx.f32 %0, %1;" : "=f"(y) : "f"(x));
    return y;
}
#define LDSM4(r0, r1, r2, r3, addr) \
    asm volatile("ldmatrix.sync.aligned.m8n8.x4.shared.b16 {%0,%1,%2,%3}, [%4];" \
                 : "=r"(r0), "=r"(r1), "=r"(r2), "=r"(r3) : "r"(addr))
#define LDSM4T(r0, r1, r2, r3, addr) \
    asm volatile("ldmatrix.sync.aligned.m8n8.x4.trans.shared.b16 {%0,%1,%2,%3}, [%4];" \
                 : "=r"(r0), "=r"(r1), "=r"(r2), "=r"(r3) : "r"(addr))
__device__ __forceinline__ void mma16816(float* d, const uint32_t* a, uint32_t b0, uint32_t b1) {
    asm volatile(
        "mma.sync.aligned.m16n8k16.row.col.f32.f16.f16.f32 "
        "{%0,%1,%2,%3}, {%4,%5,%6,%7}, {%8,%9}, {%0,%1,%2,%3};"
        : "+f"(d[0]), "+f"(d[1]), "+f"(d[2]), "+f"(d[3])
        : "r"(a[0]), "r"(a[1]), "r"(a[2]), "r"(a[3]), "r"(b0), "r"(b1));
}
__device__ __forceinline__ void cp16(uint32_t s, const void* g) {
    asm volatile("cp.async.ca.shared.global [%0], [%1], 16;" :: "r"(s), "l"(g));
}
#define CP_COMMIT() asm volatile("cp.async.commit_group;" ::: "memory")
#define CP_WAIT1() asm volatile("cp.async.wait_group 1;" ::: "memory")
#define CP_WAIT0() asm volatile("cp.async.wait_group 0;" ::: "memory")

// pack 8 floats -> hi uint4 and lo uint4 (lo = v - hi)
__device__ __forceinline__ void split8(const float* v, uint4& hi4, uint4& lo4) {
    __half2 h[4], l[4];
    #pragma unroll
    for (int i = 0; i < 4; i++) {
        h[i] = __floats2half2_rn(v[2 * i], v[2 * i + 1]);
        float2 hf = __half22float2(h[i]);
        l[i] = __floats2half2_rn(v[2 * i] - hf.x, v[2 * i + 1] - hf.y);
    }
    hi4.x = *reinterpret_cast<uint32_t*>(&h[0]);
    hi4.y = *reinterpret_cast<uint32_t*>(&h[1]);
    hi4.z = *reinterpret_cast<uint32_t*>(&h[2]);
    hi4.w = *reinterpret_cast<uint32_t*>(&h[3]);
    lo4.x = *reinterpret_cast<uint32_t*>(&l[0]);
    lo4.y = *reinterpret_cast<uint32_t*>(&l[1]);
    lo4.z = *reinterpret_cast<uint32_t*>(&l[2]);
    lo4.w = *reinterpret_cast<uint32_t*>(&l[3]);
}

// ---------------- init x = dec_input[:,0,:] ----------------
__global__ void copy_x_kernel(const float* __restrict__ dec) {
    int i = blockIdx.x * 256 + threadIdx.x;
    float v = dec[i];
    g_x[i] = v;
    int b = i >> 10, u = i & 1023;
    __half hi = __float2half_rn(v);
    g_inph[b * 2048 + u] = hi;
    g_inph[APLANE + b * 2048 + u] = __float2half_rn(v - __half2float(hi));
}

// ---------------- enc fp32 -> fp16 streaming ----------------
__global__ void ench_kernel(const float* __restrict__ enc) {
    size_t i = ((size_t)blockIdx.x * 256 + threadIdx.x) * 8;
    float4 v0 = *(const float4*)(enc + i);
    float4 v1 = *(const float4*)(enc + i + 4);
    __half2 h0 = __floats2half2_rn(v0.x, v0.y);
    __half2 h1 = __floats2half2_rn(v0.z, v0.w);
    __half2 h2 = __floats2half2_rn(v1.x, v1.y);
    __half2 h3 = __floats2half2_rn(v1.z, v1.w);
    uint4 u;
    u.x = *reinterpret_cast<uint32_t*>(&h0);
    u.y = *reinterpret_cast<uint32_t*>(&h1);
    u.z = *reinterpret_cast<uint32_t*>(&h2);
    u.w = *reinterpret_cast<uint32_t*>(&h3);
    *reinterpret_cast<uint4*>(g_ench + i) = u;
}

// ---------------- convert W1[k][n] -> g_W1h[n][k] fp16 ----------------
__global__ void conv_w1_kernel(const float* __restrict__ W1) {
    __shared__ float t[32][33];
    int n0 = blockIdx.x * 32, k0 = blockIdx.y * 32;
    int x = threadIdx.x, y = threadIdx.y;
    #pragma unroll
    for (int i = 0; i < 32; i += 8)
        t[y + i][x] = W1[(size_t)(k0 + y + i) * Un + n0 + x];
    __syncthreads();
    #pragma unroll
    for (int i = 0; i < 32; i += 8)
        g_W1h[(size_t)(n0 + y + i) * Un + k0 + x] = __float2half_rn(t[x][y + i]);
}

// ---------------- q2: 64-way k-split GEMM ----------------
__global__ __launch_bounds__(256) void q2_split_kernel(const float* __restrict__ qh,
                                                       const float* __restrict__ W2) {
    __shared__ float qs[16][68];
    const int tid = threadIdx.x;
    const int vt = blockIdx.x;      // 8 v-tiles of 128
    const int ks = blockIdx.y;      // 64 k-splits of 16
    const int v = vt * 128 + (tid & 127);
    const int half = tid >> 7;
    const int k0 = ks * 16;

    for (int i = tid; i < 64 * 16; i += 256) {
        int b = i >> 4, k = i & 15;
        qs[k][b] = qh[b * Un + k0 + k];
    }
    __syncthreads();

    float acc[32];
    #pragma unroll
    for (int j = 0; j < 32; j++) acc[j] = 0.f;

    #pragma unroll 1
    for (int k = 0; k < 16; k++) {
        float w = W2[(size_t)(k0 + k) * Un + v];
        const float4* qrow = (const float4*)&qs[k][half * 32];
        #pragma unroll
        for (int j4 = 0; j4 < 8; j4++) {
            float4 q = qrow[j4];
            acc[j4 * 4 + 0] += w * q.x;
            acc[j4 * 4 + 1] += w * q.y;
            acc[j4 * 4 + 2] += w * q.z;
            acc[j4 * 4 + 3] += w * q.w;
        }
    }
    #pragma unroll
    for (int j = 0; j < 32; j++)
        g_q2p[ks][half * 32 + j][v] = acc[j];
}

__global__ void q2_fin_kernel(const float* __restrict__ b1, const float* __restrict__ b2) {
    int i = blockIdx.x * 256 + threadIdx.x;
    int b = i >> 10, v = i & 1023;
    float s = b1[v] + b2[v];
    #pragma unroll
    for (int ks = 0; ks < 64; ks++) s += g_q2p[ks][b][v];
    g_q2[i] = s;
}

// ========== HMMA fused score GEMM (M=128, 512 threads, 16 warps 4m x 4n, 2-stage) ==========
#define SCOFF_Q2 98304
#define SCOFF_AV 102400
#define SCOFF_RED 106496   // 512 floats
#define SC_SMEM 108544

__global__ __launch_bounds__(512, 1)
void score_mma_kernel(const float* __restrict__ attnV, const float* __restrict__ attnbV) {
    extern __shared__ char smem[];
    const uint32_t sb = smem_u32(smem);
    const int tid = threadIdx.x;
    const int lane = tid & 31;
    const int wid = tid >> 5;
    const int wm = wid & 3;      // rows wm*32..+32
    const int wn = wid >> 2;     // cols wn*64..+64 of 256-tile
    const int b = blockIdx.y;
    const int s0 = blockIdx.x * 128;

    float* q2s = (float*)(smem + SCOFF_Q2);
    float* avs = (float*)(smem + SCOFF_AV);
    float* red = (float*)(smem + SCOFF_RED);

    for (int i = tid; i < Un; i += 512) {
        q2s[i] = g_q2[b * Un + i];
        avs[i] = attnV[i];
    }

    const __half* panel = g_ench + ((size_t)b * Sn + s0) * Un;

    // A stage loader: 128 rows x 64k = 1024 chunks, 2/thread
    auto loadA = [&](int kk, int buf) {
        #pragma unroll
        for (int h = 0; h < 2; h++) {
            int id = h * 512 + tid;
            int r = id >> 3;
            int c = id & 7;
            cp16(sb + buf * 16384 + r * 128 + ((c ^ (r & 7)) << 4),
                 panel + (size_t)r * Un + kk * 64 + c * 8);
        }
    };
    // B stage loader: 256n x 64k = 2048 chunks, 4/thread
    auto loadB = [&](int nt, int kk, int buf) {
        #pragma unroll
        for (int h = 0; h < 4; h++) {
            int ch = h * 512 + tid;
            int n = ch >> 3;
            int ck = ch & 7;
            cp16(sb + 32768 + buf * 32768 + n * 128 + ((ck ^ (n & 7)) << 4),
                 g_W1h + (size_t)(nt * 256 + n) * Un + kk * 64 + ck * 8);
        }
    };

    // A ldsm bases: two 16-row tiles per warp
    const int ahi = lane >> 4;
    const int arow0 = wm * 32 + (lane & 15);
    const int arow1 = arow0 + 16;
    const uint32_t ao0 = arow0 * 128;
    const uint32_t ao1 = arow1 * 128;
    const int ax0 = arow0 & 7, ax1 = arow1 & 7;

    // B ldsm bases (4 col-tiles of 16)
    const int bhi = lane >> 4;
    uint32_t bno[4];
    int bxr[4];
    #pragma unroll
    for (int bt = 0; bt < 4; bt++) {
        int bn = wn * 64 + bt * 16 + (lane & 15);
        bno[bt] = bn * 128;
        bxr[bt] = bn & 7;
    }

    const int g = lane >> 2;
    const int t = lane & 3;
    float pa[4];
    #pragma unroll
    for (int i = 0; i < 4; i++) pa[i] = 0.f;

    float dacc[16][4];

    loadA(0, 0);
    loadB(0, 0, 0);
    CP_COMMIT();

    #pragma unroll 1
    for (int idx = 0; idx < 64; idx++) {
        const int nt = idx >> 4;
        const int kk = idx & 15;
        const int buf = idx & 1;
        if (kk == 0) {
            #pragma unroll
            for (int i = 0; i < 16; i++)
                #pragma unroll
                for (int j = 0; j < 4; j++) dacc[i][j] = 0.f;
        }
        if (idx < 63) {
            int nidx = idx + 1;
            loadA(nidx & 15, nidx & 1);
            loadB(nidx >> 4, nidx & 15, nidx & 1);
            CP_COMMIT();
            CP_WAIT1();
        } else {
            CP_WAIT0();
        }
        __syncthreads();
        const uint32_t ast = sb + buf * 16384;
        const uint32_t bst = sb + 32768 + buf * 32768;
        #pragma unroll
        for (int kk2 = 0; kk2 < 4; kk2++) {
            uint32_t a0[4], a1[4];
            const int ck = kk2 * 2;
            LDSM4(a0[0], a0[1], a0[2], a0[3], ast + ao0 + (((ck + ahi) ^ ax0) << 4));
            LDSM4(a1[0], a1[1], a1[2], a1[3], ast + ao1 + (((ck + ahi) ^ ax1) << 4));
            const int bck = ck + bhi;
            #pragma unroll
            for (int bt = 0; bt < 4; bt++) {
                uint32_t q[4];
                LDSM4(q[0], q[1], q[2], q[3], bst + bno[bt] + ((bck ^ bxr[bt]) << 4));
                mma16816(dacc[0 + bt * 2 + 0], a0, q[0], q[2]);
                mma16816(dacc[0 + bt * 2 + 1], a0, q[1], q[3]);
                mma16816(dacc[8 + bt * 2 + 0], a1, q[0], q[2]);
                mma16816(dacc[8 + bt * 2 + 1], a1, q[1], q[3]);
            }
        }
        __syncthreads();
        if (kk == 15) {
            // epilogue for this n-tile: tanh(D + q2) * attnV
            #pragma unroll
            for (int at = 0; at < 2; at++)
                #pragma unroll
                for (int bt = 0; bt < 4; bt++)
                    #pragma unroll
                    for (int h = 0; h < 2; h++) {
                        const float* dd = dacc[at * 8 + bt * 2 + h];
                        int c0 = nt * 256 + wn * 64 + bt * 16 + h * 8 + 2 * t;
                        float qa = q2s[c0], qb = q2s[c0 + 1];
                        float va = avs[c0], vb = avs[c0 + 1];
                        pa[at * 2 + 0] += tanh_fast(dd[0] + qa) * va + tanh_fast(dd[1] + qb) * vb;
                        pa[at * 2 + 1] += tanh_fast(dd[2] + qa) * va + tanh_fast(dd[3] + qb) * vb;
                    }
        }
    }
    #pragma unroll
    for (int i = 0; i < 4; i++) {
        pa[i] += __shfl_xor_sync(0xffffffffu, pa[i], 1);
        pa[i] += __shfl_xor_sync(0xffffffffu, pa[i], 2);
    }
    if (t == 0) {
        #pragma unroll
        for (int at = 0; at < 2; at++)
            #pragma unroll
            for (int hh = 0; hh < 2; hh++)
                red[wn * 128 + wm * 32 + at * 16 + hh * 8 + g] = pa[at * 2 + hh];
    }
    __syncthreads();
    if (tid < 128) {
        g_score[b * Sn + s0 + tid] =
            red[tid] + red[128 + tid] + red[256 + tid] + red[384 + tid] + attnbV[0];
    }
}

// ---------------- softmax over S ----------------
__global__ void softmax_s_kernel(float* __restrict__ out_attnw) {
    int b = blockIdx.x;
    int tid = threadIdx.x;
    __shared__ float red[256];
    float m = -1e30f;
    for (int s = tid; s < Sn; s += 256) m = fmaxf(m, g_score[b * Sn + s]);
    red[tid] = m; __syncthreads();
    for (int o = 128; o > 0; o >>= 1) { if (tid < o) red[tid] = fmaxf(red[tid], red[tid + o]); __syncthreads(); }
    m = red[0]; __syncthreads();
    float sum = 0.f;
    for (int s = tid; s < Sn; s += 256) {
        float e = expf(g_score[b * Sn + s] - m);
        g_attnw[b * Sn + s] = e;
        sum += e;
    }
    red[tid] = sum; __syncthreads();
    for (int o = 128; o > 0; o >>= 1) { if (tid < o) red[tid] += red[tid + o]; __syncthreads(); }
    float inv = 1.f / red[0];
    for (int s = tid; s < Sn; s += 256) {
        float w = g_attnw[b * Sn + s] * inv;
        g_attnw[b * Sn + s] = w;
        out_attnw[b * Sn + s] = w;
    }
}

// ---------------- ctx partials: 8 s-splits, half2 loads ----------------
__global__ void ctx_part_kernel() {
    int b = blockIdx.x;
    int u0 = (blockIdx.y * 128 + threadIdx.x) * 2;
    int ss = blockIdx.z;
    const __half2* e = (const __half2*)(g_ench + (size_t)b * Sn * Un +
                                        (size_t)(ss * 256) * Un + u0);
    const float* w = g_attnw + b * Sn + ss * 256;
    float ax = 0.f, ay = 0.f;
    #pragma unroll 4
    for (int s = 0; s < 256; s++) {
        float2 v = __half22float2(e[(size_t)s * (Un / 2)]);
        float ws = w[s];
        ax += ws * v.x;
        ay += ws * v.y;
    }
    g_ctxp[ss][b][u0] = ax;
    g_ctxp[ss][b][u0 + 1] = ay;
}

__global__ void ctx_fin_kernel() {
    int i = blockIdx.x * 256 + threadIdx.x;
    int b = i >> 10, u = i & 1023;
    float c = 0.f;
    #pragma unroll
    for (int ss = 0; ss < 8; ss++) c += g_ctxp[ss][b][u];
    __half hi = __float2half_rn(c);
    g_inph[b * 2048 + 1024 + u] = hi;
    g_inph[APLANE + b * 2048 + 1024 + u] = __float2half_rn(c - __half2float(hi));
}

// =================== LSTM GEMM: 8-way k-split pipelined split-fp16 HMMA ===================
__global__ __launch_bounds__(128)
void lstm_mma_kernel(const float* __restrict__ W) {
    __shared__ __align__(128) char sm[65536];
    const uint32_t sb = smem_u32(sm);
    const int tid = threadIdx.x, lane = tid & 31, wid = tid >> 5;
    const int wm = wid & 1, wn = wid >> 1;
    const int nt = blockIdx.x;
    const int ks = blockIdx.y;
    const int k0 = ks * 256;
    const int wcol0 = nt * 64 + (nt >= 16 ? 1024 : 0);
    const int zcol0 = nt * 64;

    float dacc[8][4];
    #pragma unroll
    for (int i = 0; i < 8; i++)
        #pragma unroll
        for (int j = 0; j < 4; j++) dacc[i][j] = 0.f;

    const int hi16 = lane >> 4;
    const int g8 = lane >> 3;
    const int r8 = lane & 7;
    const int arow0 = wm * 32 + (lane & 15);
    const int arow1 = arow0 + 16;

    auto loadW = [&](int kk, float* wv) {
        #pragma unroll
        for (int j = 0; j < 4; j++) {
            int ch = j * 128 + tid;
            int k = ch >> 3, c = ch & 7;
            const float* src = W + (size_t)(k0 + kk * 64 + k) * 4096 + wcol0 + c * 8;
            float4 s0 = *(const float4*)src;
            float4 s1 = *(const float4*)(src + 4);
            wv[j * 8 + 0] = s0.x; wv[j * 8 + 1] = s0.y; wv[j * 8 + 2] = s0.z; wv[j * 8 + 3] = s0.w;
            wv[j * 8 + 4] = s1.x; wv[j * 8 + 5] = s1.y; wv[j * 8 + 6] = s1.z; wv[j * 8 + 7] = s1.w;
        }
    };
    auto stsB = [&](const float* wv, int buf) {
        #pragma unroll
        for (int j = 0; j < 4; j++) {
            int ch = j * 128 + tid;
            int k = ch >> 3, c = ch & 7;
            uint4 hi4, lo4;
            split8(wv + j * 8, hi4, lo4);
            int off = 32768 + buf * 16384 + k * 128 + ((c ^ (k & 7)) << 4);
            *(uint4*)(sm + off) = hi4;
            *(uint4*)(sm + off + 8192) = lo4;
        }
    };
    auto cpA = [&](int kk, int st) {
        #pragma unroll
        for (int j = 0; j < 8; j++) {
            int ch = j * 128 + tid;
            int plane = ch >> 9, cc = ch & 511;
            int m = cc >> 3, c = cc & 7;
            cp16(sb + st * 16384 + plane * 8192 + m * 128 + ((c ^ (m & 7)) << 4),
                 g_inph + (size_t)plane * APLANE + (size_t)m * 2048 + k0 + kk * 64 + c * 8);
        }
    };

    float wv[32], wv2[32];
    loadW(0, wv);
    cpA(0, 0);
    CP_COMMIT();

    #pragma unroll 1
    for (int kk = 0; kk < 4; kk++) {
        const int buf = kk & 1;
        stsB(wv, buf);
        if (kk < 3) loadW(kk + 1, wv2);
        CP_WAIT0();
        __syncthreads();
        if (kk < 3) { cpA(kk + 1, buf ^ 1); CP_COMMIT(); }
        #pragma unroll
        for (int seg = 0; seg < 3; seg++) {
            const uint32_t abase = sb + buf * 16384 + (seg == 2 ? 8192 : 0);
            const uint32_t bbase = sb + 32768 + buf * 16384 + (seg == 1 ? 8192 : 0);
            #pragma unroll
            for (int kk2 = 0; kk2 < 4; kk2++) {
                uint32_t a0[4], a1[4];
                int ck = kk2 * 2 + hi16;
                LDSM4(a0[0], a0[1], a0[2], a0[3],
                      abase + arow0 * 128 + ((ck ^ (arow0 & 7)) << 4));
                LDSM4(a1[0], a1[1], a1[2], a1[3],
                      abase + arow1 * 128 + ((ck ^ (arow1 & 7)) << 4));
                int kloc = kk2 * 16 + (g8 & 1) * 8 + r8;
                #pragma unroll
                for (int bt = 0; bt < 2; bt++) {
                    int nchunk = wn * 4 + bt * 2 + (g8 >> 1);
                    uint32_t q[4];
                    LDSM4T(q[0], q[1], q[2], q[3],
                           bbase + kloc * 128 + ((nchunk ^ (kloc & 7)) << 4));
                    mma16816(dacc[0 + bt * 2 + 0], a0, q[0], q[1]);
                    mma16816(dacc[0 + bt * 2 + 1], a0, q[2], q[3]);
                    mma16816(dacc[4 + bt * 2 + 0], a1, q[0], q[1]);
                    mma16816(dacc[4 + bt * 2 + 1], a1, q[2], q[3]);
                }
            }
        }
        #pragma unroll
        for (int j = 0; j < 32; j++) wv[j] = wv2[j];
        __syncthreads();
    }
    const int g = lane >> 2;
    const int t = lane & 3;
    float* zp = g_zp8 + (size_t)ks * Bn * 3072;
    #pragma unroll
    for (int at = 0; at < 2; at++)
        #pragma unroll
        for (int bt = 0; bt < 2; bt++)
            #pragma unroll
            for (int h = 0; h < 2; h++) {
                const float* dd = dacc[at * 4 + bt * 2 + h];
                int c0 = zcol0 + wn * 32 + bt * 16 + h * 8 + 2 * t;
                int r0 = wm * 32 + at * 16 + g;
                zp[(size_t)r0 * 3072 + c0] = dd[0];
                zp[(size_t)r0 * 3072 + c0 + 1] = dd[1];
                zp[(size_t)(r0 + 8) * 3072 + c0] = dd[2];
                zp[(size_t)(r0 + 8) * 3072 + c0 + 1] = dd[3];
            }
}

// ---------------- LSTM activation: sum 8 partials ----------------
__global__ void lstm_act_kernel(const float* __restrict__ lb,
                                float* __restrict__ hs, float* __restrict__ cs,
                                int layer, int residual) {
    int b = blockIdx.x;
    int u = threadIdx.x;
    float zi = lb[u], zg = lb[2048 + u], zo = lb[3072 + u];
    #pragma unroll
    for (int ks = 0; ks < 8; ks++) {
        const float* zp = g_zp8 + ((size_t)ks * Bn + b) * 3072;
        zi += zp[u];
        zg += zp[1024 + u];
        zo += zp[2048 + u];
    }
    float c = (1.f / (1.f + expf(-zi))) * tanhf(zg);
    float h = (1.f / (1.f + expf(-zo))) * tanhf(c);
    size_t o = ((size_t)layer * Bn + b) * Un + u;
    hs[o] = h;
    cs[o] = c;
    float xo = g_x[b * Un + u];
    float xn = residual ? (h + xo) : h;
    g_x[b * Un + u] = xn;
    __half hhi = __float2half_rn(xn);
    g_inph[b * 2048 + u] = hhi;
    g_inph[APLANE + b * 2048 + u] = __float2half_rn(xn - __half2float(hhi));
}

// =================== dense GEMM: pipelined fused-conversion split-fp16 HMMA ===================
__global__ __launch_bounds__(128)
void dense_mma_kernel(const float* __restrict__ W, const float* __restrict__ db) {
    __shared__ __align__(128) char sm[65536];
    const uint32_t sb = smem_u32(sm);
    const int tid = threadIdx.x, lane = tid & 31, wid = tid >> 5;
    const int wm = wid & 1, wn = wid >> 1;
    const int n0 = blockIdx.x * 64;

    float dacc[8][4];
    #pragma unroll
    for (int i = 0; i < 8; i++)
        #pragma unroll
        for (int j = 0; j < 4; j++) dacc[i][j] = 0.f;

    const int hi16 = lane >> 4;
    const int g8 = lane >> 3;
    const int r8 = lane & 7;
    const int arow0 = wm * 32 + (lane & 15);
    const int arow1 = arow0 + 16;

    auto loadW = [&](int kk, float* wv) {
        #pragma unroll
        for (int j = 0; j < 4; j++) {
            int ch = j * 128 + tid;
            int k = ch >> 3, c = ch & 7;
            const float* src = W + (size_t)(kk * 64 + k) * Vn + n0 + c * 8;
            #pragma unroll
            for (int e = 0; e < 8; e++) {
                int ng = n0 + c * 8 + e;
                wv[j * 8 + e] = (ng < Vn) ? src[e] : 0.f;
            }
        }
    };
    auto stsB = [&](const float* wv, int buf) {
        #pragma unroll
        for (int j = 0; j < 4; j++) {
            int ch = j * 128 + tid;
            int k = ch >> 3, c = ch & 7;
            uint4 hi4, lo4;
            split8(wv + j * 8, hi4, lo4);
            int off = 32768 + buf * 16384 + k * 128 + ((c ^ (k & 7)) << 4);
            *(uint4*)(sm + off) = hi4;
            *(uint4*)(sm + off + 8192) = lo4;
        }
    };
    auto cpA = [&](int kk, int st) {
        #pragma unroll
        for (int j = 0; j < 8; j++) {
            int ch = j * 128 + tid;
            int plane = ch >> 9, cc = ch & 511;
            int m = cc >> 3, c = cc & 7;
            cp16(sb + st * 16384 + plane * 8192 + m * 128 + ((c ^ (m & 7)) << 4),
                 g_inph + (size_t)plane * APLANE + (size_t)m * 2048 + kk * 64 + c * 8);
        }
    };

    float wv[32], wv2[32];
    loadW(0, wv);
    cpA(0, 0);
    CP_COMMIT();

    #pragma unroll 1
    for (int kk = 0; kk < 16; kk++) {
        const int buf = kk & 1;
        stsB(wv, buf);
        if (kk < 15) loadW(kk + 1, wv2);
        CP_WAIT0();
        __syncthreads();
        if (kk < 15) { cpA(kk + 1, buf ^ 1); CP_COMMIT(); }
        #pragma unroll
        for (int seg = 0; seg < 3; seg++) {
            const uint32_t abase = sb + buf * 16384 + (seg == 2 ? 8192 : 0);
            const uint32_t bbase = sb + 32768 + buf * 16384 + (seg == 1 ? 8192 : 0);
            #pragma unroll
            for (int kk2 = 0; kk2 < 4; kk2++) {
                uint32_t a0[4], a1[4];
                int ck = kk2 * 2 + hi16;
                LDSM4(a0[0], a0[1], a0[2], a0[3],
                      abase + arow0 * 128 + ((ck ^ (arow0 & 7)) << 4));
                LDSM4(a1[0], a1[1], a1[2], a1[3],
                      abase + arow1 * 128 + ((ck ^ (arow1 & 7)) << 4));
                int kloc = kk2 * 16 + (g8 & 1) * 8 + r8;
                #pragma unroll
                for (int bt = 0; bt < 2; bt++) {
                    int nchunk = wn * 4 + bt * 2 + (g8 >> 1);
                    uint32_t q[4];
                    LDSM4T(q[0], q[1], q[2], q[3],
                           bbase + kloc * 128 + ((nchunk ^ (kloc & 7)) << 4));
                    mma16816(dacc[0 + bt * 2 + 0], a0, q[0], q[1]);
                    mma16816(dacc[0 + bt * 2 + 1], a0, q[2], q[3]);
                    mma16816(dacc[4 + bt * 2 + 0], a1, q[0], q[1]);
                    mma16816(dacc[4 + bt * 2 + 1], a1, q[2], q[3]);
                }
            }
        }
        #pragma unroll
        for (int j = 0; j < 32; j++) wv[j] = wv2[j];
        __syncthreads();
    }
    const int g = lane >> 2;
    const int t = lane & 3;
    #pragma unroll
    for (int at = 0; at < 2; at++)
        #pragma unroll
        for (int bt = 0; bt < 2; bt++)
            #pragma unroll
            for (int h = 0; h < 2; h++) {
                const float* dd = dacc[at * 4 + bt * 2 + h];
                int c0 = n0 + wn * 32 + bt * 16 + h * 8 + 2 * t;
                int r0 = wm * 32 + at * 16 + g;
                if (c0 < Vn) {
                    float bb = db[c0];
                    g_logits[(size_t)r0 * Vn + c0] = dd[0] + bb;
                    g_logits[(size_t)(r0 + 8) * Vn + c0] = dd[2] + bb;
                }
                if (c0 + 1 < Vn) {
                    float bb = db[c0 + 1];
                    g_logits[(size_t)r0 * Vn + c0 + 1] = dd[1] + bb;
                    g_logits[(size_t)(r0 + 8) * Vn + c0 + 1] = dd[3] + bb;
                }
            }
}

// ---------------- softmax over V -> probs ----------------
__global__ void softmax_v_kernel(float* __restrict__ probs) {
    int b = blockIdx.x;
    int tid = threadIdx.x;
    __shared__ float red[1024];
    const float* lg = g_logits + (size_t)b * Vn;
    float m = -1e30f;
    for (int j = tid; j < Vn; j += 1024) m = fmaxf(m, lg[j]);
    red[tid] = m; __syncthreads();
    for (int o = 512; o > 0; o >>= 1) { if (tid < o) red[tid] = fmaxf(red[tid], red[tid + o]); __syncthreads(); }
    m = red[0]; __syncthreads();
    float sum = 0.f;
    float* pb = probs + (size_t)b * Vn;
    for (int j = tid; j < Vn; j += 1024) {
        float e = expf(lg[j] - m);
        pb[j] = e;
        sum += e;
    }
    red[tid] = sum; __syncthreads();
    for (int o = 512; o > 0; o >>= 1) { if (tid < o) red[tid] += red[tid + o]; __syncthreads(); }
    float inv = 1.f / red[0];
    for (int j = tid; j < Vn; j += 1024) pb[j] *= inv;
}

// ---------------- launch ----------------
extern "C" void kernel_launch(void* const* d_in, const int* in_sizes, int n_in,
                              void* d_out, int out_size) {
    const float* enc = (const float*)d_in[0];
    const float* dec = (const float*)d_in[1];
    const float* qh  = (const float*)d_in[2];
    const float* W1  = (const float*)d_in[3];
    const float* b1  = (const float*)d_in[4];
    const float* W2  = (const float*)d_in[5];
    const float* b2  = (const float*)d_in[6];
    const float* aV  = (const float*)d_in[7];
    const float* abV = (const float*)d_in[8];
    const float* lW  = (const float*)d_in[9];
    const float* lb  = (const float*)d_in[10];
    const float* dW  = (const float*)d_in[11];
    const float* db  = (const float*)d_in[12];

    float* out   = (float*)d_out;
    float* probs = out;
    float* hs    = out + (size_t)Bn * Vn;
    float* cs    = hs + (size_t)Ln * Bn * Un;
    float* attnw = cs + (size_t)Ln * Bn * Un;

    static const int RES[8] = {0, 0, 1, 1, 1, 1, 1, 0};

    cudaFuncSetAttribute(score_mma_kernel,
                         cudaFuncAttributeMaxDynamicSharedMemorySize, SC_SMEM);

    copy_x_kernel<<<256, 256>>>(dec);
    ench_kernel<<<65536, 256>>>(enc);
    conv_w1_kernel<<<dim3(32, 32), dim3(32, 8)>>>(W1);
    q2_split_kernel<<<dim3(8, 64), 256>>>(qh, W2);
    q2_fin_kernel<<<256, 256>>>(b1, b2);
    score_mma_kernel<<<dim3(Sn / 128, Bn), 512, SC_SMEM>>>(aV, abV);
    softmax_s_kernel<<<Bn, 256>>>(attnw);
    ctx_part_kernel<<<dim3(Bn, 4, 8), 128>>>();
    ctx_fin_kernel<<<256, 256>>>();

    for (int l = 0; l < Ln; l++) {
        lstm_mma_kernel<<<dim3(48, 8), 128>>>(lW + (size_t)l * 2048 * 4096);
        lstm_act_kernel<<<Bn, 1024>>>(lb + (size_t)l * 4096, hs, cs, l, RES[l]);
    }

    dense_mma_kernel<<<VnP / 64, 128>>>(dW, db);
    softmax_v_kernel<<<Bn, 1024>>>(probs);
}

// round 16
// speedup vs baseline: 1.0572x; 1.0327x over previous
#include <cuda_runtime.h>
#include <cuda_fp16.h>
#include <math.h>
#include <stdint.h>

#define Bn 64
#define Sn 2048
#define Un 1024
#define Vn 50257
#define VnP 50304
#define Ln 8

// ---------------- scratch (device globals; no allocs allowed) ----------------
__device__ float g_q2[Bn * Un];
__device__ float g_q2p[64][Bn][Un];                    // q2 k-split partials
__device__ float g_ctxp[8][Bn][Un];                    // ctx s-split partials
__device__ float g_score[Bn * Sn];
__device__ float g_attnw[Bn * Sn];
__device__ float g_x[Bn * Un];
__device__ float g_zp8[8 * Bn * 3072];                 // lstm k-split partials (i|g|o)
__device__ float g_logits[(size_t)Bn * Vn];
__device__ __half g_W1h[(size_t)Un * Un];              // W1^T [n][k] fp16
__device__ __half g_ench[(size_t)Bn * Sn * Un];        // enc as fp16
__device__ __half g_inph[2 * Bn * 2048];               // [plane][b][x|ctx] hi/lo

#define APLANE ((size_t)Bn * 2048)

// ======================= helpers =======================
__device__ __forceinline__ uint32_t smem_u32(const void* p) {
    uint32_t a;
    asm("{ .reg .u64 t; cvta.to.shared.u64 t, %1; cvt.u32.u64 %0, t; }" : "=r"(a) : "l"(p));
    return a;
}
__device__ __forceinline__ float tanh_fast(float x) {
    float y;
    asm("tanh.approx.f32 %0, %1;" : "=f"(y) : "f"(x));
    return y;
}
#define LDSM4(r0, r1, r2, r3, addr) \
    asm volatile("ldmatrix.sync.aligned.m8n8.x4.shared.b16 {%0,%1,%2,%3}, [%4];" \
                 : "=r"(r0), "=r"(r1), "=r"(r2), "=r"(r3) : "r"(addr))
#define LDSM4T(r0, r1, r2, r3, addr) \
    asm volatile("ldmatrix.sync.aligned.m8n8.x4.trans.shared.b16 {%0,%1,%2,%3}, [%4];" \
                 : "=r"(r0), "=r"(r1), "=r"(r2), "=r"(r3) : "r"(addr))
__device__ __forceinline__ void mma16816(float* d, const uint32_t* a, uint32_t b0, uint32_t b1) {
    asm volatile(
        "mma.sync.aligned.m16n8k16.row.col.f32.f16.f16.f32 "
        "{%0,%1,%2,%3}, {%4,%5,%6,%7}, {%8,%9}, {%0,%1,%2,%3};"
        : "+f"(d[0]), "+f"(d[1]), "+f"(d[2]), "+f"(d[3])
        : "r"(a[0]), "r"(a[1]), "r"(a[2]), "r"(a[3]), "r"(b0), "r"(b1));
}
__device__ __forceinline__ void cp16(uint32_t s, const void* g) {
    asm volatile("cp.async.ca.shared.global [%0], [%1], 16;" :: "r"(s), "l"(g));
}
#define CP_COMMIT() asm volatile("cp.async.commit_group;" ::: "memory")
#define CP_WAIT1() asm volatile("cp.async.wait_group 1;" ::: "memory")
#define CP_WAIT0() asm volatile("cp.async.wait_group 0;" ::: "memory")

// pack 8 floats -> hi uint4 and lo uint4 (lo = v - hi)
__device__ __forceinline__ void split8(const float* v, uint4& hi4, uint4& lo4) {
    __half2 h[4], l[4];
    #pragma unroll
    for (int i = 0; i < 4; i++) {
        h[i] = __floats2half2_rn(v[2 * i], v[2 * i + 1]);
        float2 hf = __half22float2(h[i]);
        l[i] = __floats2half2_rn(v[2 * i] - hf.x, v[2 * i + 1] - hf.y);
    }
    hi4.x = *reinterpret_cast<uint32_t*>(&h[0]);
    hi4.y = *reinterpret_cast<uint32_t*>(&h[1]);
    hi4.z = *reinterpret_cast<uint32_t*>(&h[2]);
    hi4.w = *reinterpret_cast<uint32_t*>(&h[3]);
    lo4.x = *reinterpret_cast<uint32_t*>(&l[0]);
    lo4.y = *reinterpret_cast<uint32_t*>(&l[1]);
    lo4.z = *reinterpret_cast<uint32_t*>(&l[2]);
    lo4.w = *reinterpret_cast<uint32_t*>(&l[3]);
}

// ---------------- init x = dec_input[:,0,:] ----------------
__global__ void copy_x_kernel(const float* __restrict__ dec) {
    int i = blockIdx.x * 256 + threadIdx.x;
    float v = dec[i];
    g_x[i] = v;
    int b = i >> 10, u = i & 1023;
    __half hi = __float2half_rn(v);
    g_inph[b * 2048 + u] = hi;
    g_inph[APLANE + b * 2048 + u] = __float2half_rn(v - __half2float(hi));
}

// ---------------- enc fp32 -> fp16 streaming ----------------
__global__ void ench_kernel(const float* __restrict__ enc) {
    size_t i = ((size_t)blockIdx.x * 256 + threadIdx.x) * 8;
    float4 v0 = *(const float4*)(enc + i);
    float4 v1 = *(const float4*)(enc + i + 4);
    __half2 h0 = __floats2half2_rn(v0.x, v0.y);
    __half2 h1 = __floats2half2_rn(v0.z, v0.w);
    __half2 h2 = __floats2half2_rn(v1.x, v1.y);
    __half2 h3 = __floats2half2_rn(v1.z, v1.w);
    uint4 u;
    u.x = *reinterpret_cast<uint32_t*>(&h0);
    u.y = *reinterpret_cast<uint32_t*>(&h1);
    u.z = *reinterpret_cast<uint32_t*>(&h2);
    u.w = *reinterpret_cast<uint32_t*>(&h3);
    *reinterpret_cast<uint4*>(g_ench + i) = u;
}

// ---------------- convert W1[k][n] -> g_W1h[n][k] fp16 ----------------
__global__ void conv_w1_kernel(const float* __restrict__ W1) {
    __shared__ float t[32][33];
    int n0 = blockIdx.x * 32, k0 = blockIdx.y * 32;
    int x = threadIdx.x, y = threadIdx.y;
    #pragma unroll
    for (int i = 0; i < 32; i += 8)
        t[y + i][x] = W1[(size_t)(k0 + y + i) * Un + n0 + x];
    __syncthreads();
    #pragma unroll
    for (int i = 0; i < 32; i += 8)
        g_W1h[(size_t)(n0 + y + i) * Un + k0 + x] = __float2half_rn(t[x][y + i]);
}

// ---------------- q2: 64-way k-split GEMM ----------------
__global__ __launch_bounds__(256) void q2_split_kernel(const float* __restrict__ qh,
                                                       const float* __restrict__ W2) {
    __shared__ float qs[16][68];
    const int tid = threadIdx.x;
    const int vt = blockIdx.x;      // 8 v-tiles of 128
    const int ks = blockIdx.y;      // 64 k-splits of 16
    const int v = vt * 128 + (tid & 127);
    const int half = tid >> 7;
    const int k0 = ks * 16;

    for (int i = tid; i < 64 * 16; i += 256) {
        int b = i >> 4, k = i & 15;
        qs[k][b] = qh[b * Un + k0 + k];
    }
    __syncthreads();

    float acc[32];
    #pragma unroll
    for (int j = 0; j < 32; j++) acc[j] = 0.f;

    #pragma unroll 1
    for (int k = 0; k < 16; k++) {
        float w = W2[(size_t)(k0 + k) * Un + v];
        const float4* qrow = (const float4*)&qs[k][half * 32];
        #pragma unroll
        for (int j4 = 0; j4 < 8; j4++) {
            float4 q = qrow[j4];
            acc[j4 * 4 + 0] += w * q.x;
            acc[j4 * 4 + 1] += w * q.y;
            acc[j4 * 4 + 2] += w * q.z;
            acc[j4 * 4 + 3] += w * q.w;
        }
    }
    #pragma unroll
    for (int j = 0; j < 32; j++)
        g_q2p[ks][half * 32 + j][v] = acc[j];
}

__global__ void q2_fin_kernel(const float* __restrict__ b1, const float* __restrict__ b2) {
    int i = blockIdx.x * 256 + threadIdx.x;
    int b = i >> 10, v = i & 1023;
    float s = b1[v] + b2[v];
    #pragma unroll
    for (int ks = 0; ks < 64; ks++) s += g_q2p[ks][b][v];
    g_q2[i] = s;
}

// ========== HMMA fused score GEMM (M=128, 512 thr, 3-stage, R9 issue order, 1 sync/iter) ==========
// stage s @ s*49152: A (128x64k fp16, 16KB) @+0, B (256n x 64k, 32KB) @+16384
#define SC_STG 49152
#define SCOFF_Q2 147456
#define SCOFF_AV 151552
#define SCOFF_RED 155648   // 512 floats
#define SC_SMEM 157696

__global__ __launch_bounds__(512, 1)
void score_mma_kernel(const float* __restrict__ attnV, const float* __restrict__ attnbV) {
    extern __shared__ char smem[];
    const uint32_t sb = smem_u32(smem);
    const int tid = threadIdx.x;
    const int lane = tid & 31;
    const int wid = tid >> 5;
    const int wm = wid & 3;      // rows wm*32..+32
    const int wn = wid >> 2;     // cols wn*64..+64 of 256-tile
    const int b = blockIdx.y;
    const int s0 = blockIdx.x * 128;

    float* q2s = (float*)(smem + SCOFF_Q2);
    float* avs = (float*)(smem + SCOFF_AV);
    float* red = (float*)(smem + SCOFF_RED);

    for (int i = tid; i < Un; i += 512) {
        q2s[i] = g_q2[b * Un + i];
        avs[i] = attnV[i];
    }

    const __half* panel = g_ench + ((size_t)b * Sn + s0) * Un;

    // A stage loader: 128 rows x 64k = 1024 chunks, 2/thread
    auto loadA = [&](int kk, int buf) {
        #pragma unroll
        for (int h = 0; h < 2; h++) {
            int id = h * 512 + tid;
            int r = id >> 3;
            int c = id & 7;
            cp16(sb + buf * SC_STG + r * 128 + ((c ^ (r & 7)) << 4),
                 panel + (size_t)r * Un + kk * 64 + c * 8);
        }
    };
    // B stage loader: 256n x 64k = 2048 chunks, 4/thread
    auto loadB = [&](int nt, int kk, int buf) {
        #pragma unroll
        for (int h = 0; h < 4; h++) {
            int ch = h * 512 + tid;
            int n = ch >> 3;
            int ck = ch & 7;
            cp16(sb + buf * SC_STG + 16384 + n * 128 + ((ck ^ (n & 7)) << 4),
                 g_W1h + (size_t)(nt * 256 + n) * Un + kk * 64 + ck * 8);
        }
    };

    // A ldsm bases: two 16-row tiles per warp
    const int ahi = lane >> 4;
    const int arow0 = wm * 32 + (lane & 15);
    const int arow1 = arow0 + 16;
    const uint32_t ao0 = arow0 * 128;
    const uint32_t ao1 = arow1 * 128;
    const int ax0 = arow0 & 7, ax1 = arow1 & 7;

    // B ldsm bases (4 col-tiles of 16)
    const int bhi = lane >> 4;
    uint32_t bno[4];
    int bxr[4];
    #pragma unroll
    for (int bt = 0; bt < 4; bt++) {
        int bn = wn * 64 + bt * 16 + (lane & 15);
        bno[bt] = bn * 128;
        bxr[bt] = bn & 7;
    }

    const int g = lane >> 2;
    const int t = lane & 3;
    float pa[4];
    #pragma unroll
    for (int i = 0; i < 4; i++) pa[i] = 0.f;

    float dacc[16][4];

    loadA(0, 0);
    loadB(0, 0, 0);
    CP_COMMIT();

    int buf = 0;
    #pragma unroll 1
    for (int idx = 0; idx < 64; idx++) {
        const int nt = idx >> 4;
        const int kk = idx & 15;
        const int nbuf = (buf == 2) ? 0 : buf + 1;
        if (kk == 0) {
            #pragma unroll
            for (int i = 0; i < 16; i++)
                #pragma unroll
                for (int j = 0; j < 4; j++) dacc[i][j] = 0.f;
        }
        // R9 issue order: loads for idx+1 FIRST (into 3rd buffer), then wait, one sync
        if (idx < 63) {
            int nidx = idx + 1;
            loadA(nidx & 15, nbuf);
            loadB(nidx >> 4, nidx & 15, nbuf);
            CP_COMMIT();
            CP_WAIT1();
        } else {
            CP_WAIT0();
        }
        __syncthreads();
        const uint32_t ast = sb + buf * SC_STG;
        const uint32_t bst = ast + 16384;
        #pragma unroll
        for (int kk2 = 0; kk2 < 4; kk2++) {
            uint32_t a0[4], a1[4];
            const int ck = kk2 * 2;
            LDSM4(a0[0], a0[1], a0[2], a0[3], ast + ao0 + (((ck + ahi) ^ ax0) << 4));
            LDSM4(a1[0], a1[1], a1[2], a1[3], ast + ao1 + (((ck + ahi) ^ ax1) << 4));
            const int bck = ck + bhi;
            #pragma unroll
            for (int bt = 0; bt < 4; bt++) {
                uint32_t q[4];
                LDSM4(q[0], q[1], q[2], q[3], bst + bno[bt] + ((bck ^ bxr[bt]) << 4));
                mma16816(dacc[0 + bt * 2 + 0], a0, q[0], q[2]);
                mma16816(dacc[0 + bt * 2 + 1], a0, q[1], q[3]);
                mma16816(dacc[8 + bt * 2 + 0], a1, q[0], q[2]);
                mma16816(dacc[8 + bt * 2 + 1], a1, q[1], q[3]);
            }
        }
        // no trailing sync: buffer `buf` is not rewritten until iter idx+2's loads,
        // which are issued after the sync at iter idx+1 (all warps past mma(idx)).
        if (kk == 15) {
            #pragma unroll
            for (int at = 0; at < 2; at++)
                #pragma unroll
                for (int bt = 0; bt < 4; bt++)
                    #pragma unroll
                    for (int h = 0; h < 2; h++) {
                        const float* dd = dacc[at * 8 + bt * 2 + h];
                        int c0 = nt * 256 + wn * 64 + bt * 16 + h * 8 + 2 * t;
                        float qa = q2s[c0], qb = q2s[c0 + 1];
                        float va = avs[c0], vb = avs[c0 + 1];
                        pa[at * 2 + 0] += tanh_fast(dd[0] + qa) * va + tanh_fast(dd[1] + qb) * vb;
                        pa[at * 2 + 1] += tanh_fast(dd[2] + qa) * va + tanh_fast(dd[3] + qb) * vb;
                    }
        }
        buf = nbuf;
    }
    #pragma unroll
    for (int i = 0; i < 4; i++) {
        pa[i] += __shfl_xor_sync(0xffffffffu, pa[i], 1);
        pa[i] += __shfl_xor_sync(0xffffffffu, pa[i], 2);
    }
    if (t == 0) {
        #pragma unroll
        for (int at = 0; at < 2; at++)
            #pragma unroll
            for (int hh = 0; hh < 2; hh++)
                red[wn * 128 + wm * 32 + at * 16 + hh * 8 + g] = pa[at * 2 + hh];
    }
    __syncthreads();
    if (tid < 128) {
        g_score[b * Sn + s0 + tid] =
            red[tid] + red[128 + tid] + red[256 + tid] + red[384 + tid] + attnbV[0];
    }
}

// ---------------- softmax over S ----------------
__global__ void softmax_s_kernel(float* __restrict__ out_attnw) {
    int b = blockIdx.x;
    int tid = threadIdx.x;
    __shared__ float red[256];
    float m = -1e30f;
    for (int s = tid; s < Sn; s += 256) m = fmaxf(m, g_score[b * Sn + s]);
    red[tid] = m; __syncthreads();
    for (int o = 128; o > 0; o >>= 1) { if (tid < o) red[tid] = fmaxf(red[tid], red[tid + o]); __syncthreads(); }
    m = red[0]; __syncthreads();
    float sum = 0.f;
    for (int s = tid; s < Sn; s += 256) {
        float e = expf(g_score[b * Sn + s] - m);
        g_attnw[b * Sn + s] = e;
        sum += e;
    }
    red[tid] = sum; __syncthreads();
    for (int o = 128; o > 0; o >>= 1) { if (tid < o) red[tid] += red[tid + o]; __syncthreads(); }
    float inv = 1.f / red[0];
    for (int s = tid; s < Sn; s += 256) {
        float w = g_attnw[b * Sn + s] * inv;
        g_attnw[b * Sn + s] = w;
        out_attnw[b * Sn + s] = w;
    }
}

// ---------------- ctx partials: 8 s-splits, half2 loads ----------------
__global__ void ctx_part_kernel() {
    int b = blockIdx.x;
    int u0 = (blockIdx.y * 128 + threadIdx.x) * 2;
    int ss = blockIdx.z;
    const __half2* e = (const __half2*)(g_ench + (size_t)b * Sn * Un +
                                        (size_t)(ss * 256) * Un + u0);
    const float* w = g_attnw + b * Sn + ss * 256;
    float ax = 0.f, ay = 0.f;
    #pragma unroll 4
    for (int s = 0; s < 256; s++) {
        float2 v = __half22float2(e[(size_t)s * (Un / 2)]);
        float ws = w[s];
        ax += ws * v.x;
        ay += ws * v.y;
    }
    g_ctxp[ss][b][u0] = ax;
    g_ctxp[ss][b][u0 + 1] = ay;
}

__global__ void ctx_fin_kernel() {
    int i = blockIdx.x * 256 + threadIdx.x;
    int b = i >> 10, u = i & 1023;
    float c = 0.f;
    #pragma unroll
    for (int ss = 0; ss < 8; ss++) c += g_ctxp[ss][b][u];
    __half hi = __float2half_rn(c);
    g_inph[b * 2048 + 1024 + u] = hi;
    g_inph[APLANE + b * 2048 + 1024 + u] = __float2half_rn(c - __half2float(hi));
}

// =================== LSTM GEMM: 8-way k-split pipelined split-fp16 HMMA ===================
__global__ __launch_bounds__(128)
void lstm_mma_kernel(const float* __restrict__ W) {
    __shared__ __align__(128) char sm[65536];
    const uint32_t sb = smem_u32(sm);
    const int tid = threadIdx.x, lane = tid & 31, wid = tid >> 5;
    const int wm = wid & 1, wn = wid >> 1;
    const int nt = blockIdx.x;
    const int ks = blockIdx.y;
    const int k0 = ks * 256;
    const int wcol0 = nt * 64 + (nt >= 16 ? 1024 : 0);
    const int zcol0 = nt * 64;

    float dacc[8][4];
    #pragma unroll
    for (int i = 0; i < 8; i++)
        #pragma unroll
        for (int j = 0; j < 4; j++) dacc[i][j] = 0.f;

    const int hi16 = lane >> 4;
    const int g8 = lane >> 3;
    const int r8 = lane & 7;
    const int arow0 = wm * 32 + (lane & 15);
    const int arow1 = arow0 + 16;

    auto loadW = [&](int kk, float* wv) {
        #pragma unroll
        for (int j = 0; j < 4; j++) {
            int ch = j * 128 + tid;
            int k = ch >> 3, c = ch & 7;
            const float* src = W + (size_t)(k0 + kk * 64 + k) * 4096 + wcol0 + c * 8;
            float4 s0 = *(const float4*)src;
            float4 s1 = *(const float4*)(src + 4);
            wv[j * 8 + 0] = s0.x; wv[j * 8 + 1] = s0.y; wv[j * 8 + 2] = s0.z; wv[j * 8 + 3] = s0.w;
            wv[j * 8 + 4] = s1.x; wv[j * 8 + 5] = s1.y; wv[j * 8 + 6] = s1.z; wv[j * 8 + 7] = s1.w;
        }
    };
    auto stsB = [&](const float* wv, int buf) {
        #pragma unroll
        for (int j = 0; j < 4; j++) {
            int ch = j * 128 + tid;
            int k = ch >> 3, c = ch & 7;
            uint4 hi4, lo4;
            split8(wv + j * 8, hi4, lo4);
            int off = 32768 + buf * 16384 + k * 128 + ((c ^ (k & 7)) << 4);
            *(uint4*)(sm + off) = hi4;
            *(uint4*)(sm + off + 8192) = lo4;
        }
    };
    auto cpA = [&](int kk, int st) {
        #pragma unroll
        for (int j = 0; j < 8; j++) {
            int ch = j * 128 + tid;
            int plane = ch >> 9, cc = ch & 511;
            int m = cc >> 3, c = cc & 7;
            cp16(sb + st * 16384 + plane * 8192 + m * 128 + ((c ^ (m & 7)) << 4),
                 g_inph + (size_t)plane * APLANE + (size_t)m * 2048 + k0 + kk * 64 + c * 8);
        }
    };

    float wv[32], wv2[32];
    loadW(0, wv);
    cpA(0, 0);
    CP_COMMIT();

    #pragma unroll 1
    for (int kk = 0; kk < 4; kk++) {
        const int buf = kk & 1;
        stsB(wv, buf);
        if (kk < 3) loadW(kk + 1, wv2);
        CP_WAIT0();
        __syncthreads();
        if (kk < 3) { cpA(kk + 1, buf ^ 1); CP_COMMIT(); }
        #pragma unroll
        for (int seg = 0; seg < 3; seg++) {
            const uint32_t abase = sb + buf * 16384 + (seg == 2 ? 8192 : 0);
            const uint32_t bbase = sb + 32768 + buf * 16384 + (seg == 1 ? 8192 : 0);
            #pragma unroll
            for (int kk2 = 0; kk2 < 4; kk2++) {
                uint32_t a0[4], a1[4];
                int ck = kk2 * 2 + hi16;
                LDSM4(a0[0], a0[1], a0[2], a0[3],
                      abase + arow0 * 128 + ((ck ^ (arow0 & 7)) << 4));
                LDSM4(a1[0], a1[1], a1[2], a1[3],
                      abase + arow1 * 128 + ((ck ^ (arow1 & 7)) << 4));
                int kloc = kk2 * 16 + (g8 & 1) * 8 + r8;
                #pragma unroll
                for (int bt = 0; bt < 2; bt++) {
                    int nchunk = wn * 4 + bt * 2 + (g8 >> 1);
                    uint32_t q[4];
                    LDSM4T(q[0], q[1], q[2], q[3],
                           bbase + kloc * 128 + ((nchunk ^ (kloc & 7)) << 4));
                    mma16816(dacc[0 + bt * 2 + 0], a0, q[0], q[1]);
                    mma16816(dacc[0 + bt * 2 + 1], a0, q[2], q[3]);
                    mma16816(dacc[4 + bt * 2 + 0], a1, q[0], q[1]);
                    mma16816(dacc[4 + bt * 2 + 1], a1, q[2], q[3]);
                }
            }
        }
        #pragma unroll
        for (int j = 0; j < 32; j++) wv[j] = wv2[j];
        __syncthreads();
    }
    const int g = lane >> 2;
    const int t = lane & 3;
    float* zp = g_zp8 + (size_t)ks * Bn * 3072;
    #pragma unroll
    for (int at = 0; at < 2; at++)
        #pragma unroll
        for (int bt = 0; bt < 2; bt++)
            #pragma unroll
            for (int h = 0; h < 2; h++) {
                const float* dd = dacc[at * 4 + bt * 2 + h];
                int c0 = zcol0 + wn * 32 + bt * 16 + h * 8 + 2 * t;
                int r0 = wm * 32 + at * 16 + g;
                zp[(size_t)r0 * 3072 + c0] = dd[0];
                zp[(size_t)r0 * 3072 + c0 + 1] = dd[1];
                zp[(size_t)(r0 + 8) * 3072 + c0] = dd[2];
                zp[(size_t)(r0 + 8) * 3072 + c0 + 1] = dd[3];
            }
}

// ---------------- LSTM activation: sum 8 partials ----------------
__global__ void lstm_act_kernel(const float* __restrict__ lb,
                                float* __restrict__ hs, float* __restrict__ cs,
                                int layer, int residual) {
    int b = blockIdx.x;
    int u = threadIdx.x;
    float zi = lb[u], zg = lb[2048 + u], zo = lb[3072 + u];
    #pragma unroll
    for (int ks = 0; ks < 8; ks++) {
        const float* zp = g_zp8 + ((size_t)ks * Bn + b) * 3072;
        zi += zp[u];
        zg += zp[1024 + u];
        zo += zp[2048 + u];
    }
    float c = (1.f / (1.f + expf(-zi))) * tanhf(zg);
    float h = (1.f / (1.f + expf(-zo))) * tanhf(c);
    size_t o = ((size_t)layer * Bn + b) * Un + u;
    hs[o] = h;
    cs[o] = c;
    float xo = g_x[b * Un + u];
    float xn = residual ? (h + xo) : h;
    g_x[b * Un + u] = xn;
    __half hhi = __float2half_rn(xn);
    g_inph[b * 2048 + u] = hhi;
    g_inph[APLANE + b * 2048 + u] = __float2half_rn(xn - __half2float(hhi));
}

// =================== dense GEMM: pipelined fused-conversion split-fp16 HMMA ===================
__global__ __launch_bounds__(128)
void dense_mma_kernel(const float* __restrict__ W, const float* __restrict__ db) {
    __shared__ __align__(128) char sm[65536];
    const uint32_t sb = smem_u32(sm);
    const int tid = threadIdx.x, lane = tid & 31, wid = tid >> 5;
    const int wm = wid & 1, wn = wid >> 1;
    const int n0 = blockIdx.x * 64;

    float dacc[8][4];
    #pragma unroll
    for (int i = 0; i < 8; i++)
        #pragma unroll
        for (int j = 0; j < 4; j++) dacc[i][j] = 0.f;

    const int hi16 = lane >> 4;
    const int g8 = lane >> 3;
    const int r8 = lane & 7;
    const int arow0 = wm * 32 + (lane & 15);
    const int arow1 = arow0 + 16;

    auto loadW = [&](int kk, float* wv) {
        #pragma unroll
        for (int j = 0; j < 4; j++) {
            int ch = j * 128 + tid;
            int k = ch >> 3, c = ch & 7;
            const float* src = W + (size_t)(kk * 64 + k) * Vn + n0 + c * 8;
            #pragma unroll
            for (int e = 0; e < 8; e++) {
                int ng = n0 + c * 8 + e;
                wv[j * 8 + e] = (ng < Vn) ? src[e] : 0.f;
            }
        }
    };
    auto stsB = [&](const float* wv, int buf) {
        #pragma unroll
        for (int j = 0; j < 4; j++) {
            int ch = j * 128 + tid;
            int k = ch >> 3, c = ch & 7;
            uint4 hi4, lo4;
            split8(wv + j * 8, hi4, lo4);
            int off = 32768 + buf * 16384 + k * 128 + ((c ^ (k & 7)) << 4);
            *(uint4*)(sm + off) = hi4;
            *(uint4*)(sm + off + 8192) = lo4;
        }
    };
    auto cpA = [&](int kk, int st) {
        #pragma unroll
        for (int j = 0; j < 8; j++) {
            int ch = j * 128 + tid;
            int plane = ch >> 9, cc = ch & 511;
            int m = cc >> 3, c = cc & 7;
            cp16(sb + st * 16384 + plane * 8192 + m * 128 + ((c ^ (m & 7)) << 4),
                 g_inph + (size_t)plane * APLANE + (size_t)m * 2048 + kk * 64 + c * 8);
        }
    };

    float wv[32], wv2[32];
    loadW(0, wv);
    cpA(0, 0);
    CP_COMMIT();

    #pragma unroll 1
    for (int kk = 0; kk < 16; kk++) {
        const int buf = kk & 1;
        stsB(wv, buf);
        if (kk < 15) loadW(kk + 1, wv2);
        CP_WAIT0();
        __syncthreads();
        if (kk < 15) { cpA(kk + 1, buf ^ 1); CP_COMMIT(); }
        #pragma unroll
        for (int seg = 0; seg < 3; seg++) {
            const uint32_t abase = sb + buf * 16384 + (seg == 2 ? 8192 : 0);
            const uint32_t bbase = sb + 32768 + buf * 16384 + (seg == 1 ? 8192 : 0);
            #pragma unroll
            for (int kk2 = 0; kk2 < 4; kk2++) {
                uint32_t a0[4], a1[4];
                int ck = kk2 * 2 + hi16;
                LDSM4(a0[0], a0[1], a0[2], a0[3],
                      abase + arow0 * 128 + ((ck ^ (arow0 & 7)) << 4));
                LDSM4(a1[0], a1[1], a1[2], a1[3],
                      abase + arow1 * 128 + ((ck ^ (arow1 & 7)) << 4));
                int kloc = kk2 * 16 + (g8 & 1) * 8 + r8;
                #pragma unroll
                for (int bt = 0; bt < 2; bt++) {
                    int nchunk = wn * 4 + bt * 2 + (g8 >> 1);
                    uint32_t q[4];
                    LDSM4T(q[0], q[1], q[2], q[3],
                           bbase + kloc * 128 + ((nchunk ^ (kloc & 7)) << 4));
                    mma16816(dacc[0 + bt * 2 + 0], a0, q[0], q[1]);
                    mma16816(dacc[0 + bt * 2 + 1], a0, q[2], q[3]);
                    mma16816(dacc[4 + bt * 2 + 0], a1, q[0], q[1]);
                    mma16816(dacc[4 + bt * 2 + 1], a1, q[2], q[3]);
                }
            }
        }
        #pragma unroll
        for (int j = 0; j < 32; j++) wv[j] = wv2[j];
        __syncthreads();
    }
    const int g = lane >> 2;
    const int t = lane & 3;
    #pragma unroll
    for (int at = 0; at < 2; at++)
        #pragma unroll
        for (int bt = 0; bt < 2; bt++)
            #pragma unroll
            for (int h = 0; h < 2; h++) {
                const float* dd = dacc[at * 4 + bt * 2 + h];
                int c0 = n0 + wn * 32 + bt * 16 + h * 8 + 2 * t;
                int r0 = wm * 32 + at * 16 + g;
                if (c0 < Vn) {
                    float bb = db[c0];
                    g_logits[(size_t)r0 * Vn + c0] = dd[0] + bb;
                    g_logits[(size_t)(r0 + 8) * Vn + c0] = dd[2] + bb;
                }
                if (c0 + 1 < Vn) {
                    float bb = db[c0 + 1];
                    g_logits[(size_t)r0 * Vn + c0 + 1] = dd[1] + bb;
                    g_logits[(size_t)(r0 + 8) * Vn + c0 + 1] = dd[3] + bb;
                }
            }
}

// ---------------- softmax over V -> probs ----------------
__global__ void softmax_v_kernel(float* __restrict__ probs) {
    int b = blockIdx.x;
    int tid = threadIdx.x;
    __shared__ float red[1024];
    const float* lg = g_logits + (size_t)b * Vn;
    float m = -1e30f;
    for (int j = tid; j < Vn; j += 1024) m = fmaxf(m, lg[j]);
    red[tid] = m; __syncthreads();
    for (int o = 512; o > 0; o >>= 1) { if (tid < o) red[tid] = fmaxf(red[tid], red[tid + o]); __syncthreads(); }
    m = red[0]; __syncthreads();
    float sum = 0.f;
    float* pb = probs + (size_t)b * Vn;
    for (int j = tid; j < Vn; j += 1024) {
        float e = expf(lg[j] - m);
        pb[j] = e;
        sum += e;
    }
    red[tid] = sum; __syncthreads();
    for (int o = 512; o > 0; o >>= 1) { if (tid < o) red[tid] += red[tid + o]; __syncthreads(); }
    float inv = 1.f / red[0];
    for (int j = tid; j < Vn; j += 1024) pb[j] *= inv;
}

// ---------------- launch ----------------
extern "C" void kernel_launch(void* const* d_in, const int* in_sizes, int n_in,
                              void* d_out, int out_size) {
    const float* enc = (const float*)d_in[0];
    const float* dec = (const float*)d_in[1];
    const float* qh  = (const float*)d_in[2];
    const float* W1  = (const float*)d_in[3];
    const float* b1  = (const float*)d_in[4];
    const float* W2  = (const float*)d_in[5];
    const float* b2  = (const float*)d_in[6];
    const float* aV  = (const float*)d_in[7];
    const float* abV = (const float*)d_in[8];
    const float* lW  = (const float*)d_in[9];
    const float* lb  = (const float*)d_in[10];
    const float* dW  = (const float*)d_in[11];
    const float* db  = (const float*)d_in[12];

    float* out   = (float*)d_out;
    float* probs = out;
    float* hs    = out + (size_t)Bn * Vn;
    float* cs    = hs + (size_t)Ln * Bn * Un;
    float* attnw = cs + (size_t)Ln * Bn * Un;

    static const int RES[8] = {0, 0, 1, 1, 1, 1, 1, 0};

    cudaFuncSetAttribute(score_mma_kernel,
                         cudaFuncAttributeMaxDynamicSharedMemorySize, SC_SMEM);

    copy_x_kernel<<<256, 256>>>(dec);
    ench_kernel<<<65536, 256>>>(enc);
    conv_w1_kernel<<<dim3(32, 32), dim3(32, 8)>>>(W1);
    q2_split_kernel<<<dim3(8, 64), 256>>>(qh, W2);
    q2_fin_kernel<<<256, 256>>>(b1, b2);
    score_mma_kernel<<<dim3(Sn / 128, Bn), 512, SC_SMEM>>>(aV, abV);
    softmax_s_kernel<<<Bn, 256>>>(attnw);
    ctx_part_kernel<<<dim3(Bn, 4, 8), 128>>>();
    ctx_fin_kernel<<<256, 256>>>();

    for (int l = 0; l < Ln; l++) {
        lstm_mma_kernel<<<dim3(48, 8), 128>>>(lW + (size_t)l * 2048 * 4096);
        lstm_act_kernel<<<Bn, 1024>>>(lb + (size_t)l * 4096, hs, cs, l, RES[l]);
    }

    dense_mma_kernel<<<VnP / 64, 128>>>(dW, db);
    softmax_v_kernel<<<Bn, 1024>>>(probs);
}